// round 6
// baseline (speedup 1.0000x reference)
#include <cuda_runtime.h>
#include <cuda_bf16.h>
#include <math.h>

// ============================================================================
// Problem: b=8, c=128, h=w=128, heads=8, hd=16, kvlen = 64+16+4+1 = 85
// ============================================================================

#define NB   8
#define NC   128
#define NH   8
#define HD   16
#define KVL  85
#define KVS  (KVL * HD)          // 1360

// device scratch (allocation-free rule: __device__ globals)
__device__ __align__(16) float d_tab[128 * 64];   // tab[y*64+j]
__device__ __align__(16) float d_tabT[64 * 128];  // tabT[j*128+p] = tab[p*64+j]
__device__ __align__(16) float d_tabR[8 * 64];    // tabR[bin*64+j] = sum_{t<16} tab[(16bin+t)*64+j]
__device__ __align__(16) float d_y1[NB * KVL * NC];   // TRANSPOSED: [b][row][c]
__device__ __align__(16) float d_pwT[128 * 128];      // pwT[ci][o]
__device__ __align__(16) float d_WkvT[128 * 256];     // WkvT[ci][o]
__device__ __align__(16) float d_k[NB * NH * KVS];
__device__ __align__(16) float d_v[NB * NH * KVS];

typedef unsigned long long u64;

// ----------------------------------------------------------------------------
// f32x2 packed math (Blackwell FFMA2: 2x fp32 FMA per issue)
// ----------------------------------------------------------------------------
__device__ __forceinline__ u64 fma2(u64 a, u64 b, u64 c) {
    u64 d;
    asm("fma.rn.f32x2 %0, %1, %2, %3;" : "=l"(d) : "l"(a), "l"(b), "l"(c));
    return d;
}
__device__ __forceinline__ u64 mul2(u64 a, u64 b) {
    u64 d;
    asm("mul.rn.f32x2 %0, %1, %2;" : "=l"(d) : "l"(a), "l"(b));
    return d;
}
__device__ __forceinline__ u64 splat2(float x) {
    u64 d;
    asm("mov.b64 %0, {%1, %1};" : "=l"(d) : "f"(x));
    return d;
}
__device__ __forceinline__ void unpack2(u64 v, float& lo, float& hi) {
    asm("mov.b64 {%0, %1}, %2;" : "=f"(lo), "=f"(hi) : "l"(v));
}

// ----------------------------------------------------------------------------
// K0: pos-enc tables + weight transposes. inv[i] = 10000^(-(2i)/64)
// ----------------------------------------------------------------------------
__global__ void k_tables(const float* __restrict__ pw, const float* __restrict__ Wkv) {
    int idx = blockIdx.x * 256 + threadIdx.x;
    if (idx < 8192) {
        int yv = idx >> 6, j = idx & 63, i = j & 31;
        float inv = powf(10000.0f, -(2.0f * (float)i) / 64.0f);
        float a = (float)yv * inv;
        d_tab[idx] = (j < 32) ? sinf(a) : cosf(a);
    } else if (idx < 16384) {
        int e = idx - 8192;
        int j = e >> 7, p = e & 127, i = j & 31;
        float inv = powf(10000.0f, -(2.0f * (float)i) / 64.0f);
        float a = (float)p * inv;
        d_tabT[e] = (j < 32) ? sinf(a) : cosf(a);
    } else if (idx < 16896) {
        int e = idx - 16384;
        int bin = e >> 6, j = e & 63, i = j & 31;
        float inv = powf(10000.0f, -(2.0f * (float)i) / 64.0f);
        float s = 0.0f;
        for (int t = 0; t < 16; ++t) {
            float a = (float)(bin * 16 + t) * inv;
            s += (j < 32) ? sinf(a) : cosf(a);
        }
        d_tabR[e] = s;
    } else if (idx < 16896 + 16384) {
        int e = idx - 16896;                 // e = ci*128 + o
        int ci = e >> 7, o = e & 127;
        d_pwT[e] = pw[o * 128 + ci];
    } else if (idx < 16896 + 16384 + 32768) {
        int e = idx - (16896 + 16384);       // e = ci*256 + o
        int ci = e >> 8, o = e & 255;
        d_WkvT[e] = Wkv[o * 128 + ci];
    }
}

// ----------------------------------------------------------------------------
// K1: per-(b,c): pool x to 8x8 means, add analytic pos-enc bin sums, derive
// 4x4/2x2/1x1 (nested means), depthwise 3x3 SAME conv -> y1[b][row][c]
// ----------------------------------------------------------------------------
__global__ void k_pool_dw(const float* __restrict__ x, const float* __restrict__ dw) {
    __shared__ float pm[64];
    __shared__ float g4[16];
    __shared__ float g2[4];
    __shared__ float g1[1];
    int tid = threadIdx.x;
    int b = blockIdx.x >> 7, c = blockIdx.x & 127;

    if (tid < 64) pm[tid] = 0.0f;
    __syncthreads();

    int r = tid >> 1, hf = tid & 1;     // row 0..127, column half
    const float4* xr = (const float4*)(x + ((size_t)(b * NC + c) << 14) + (r << 7) + (hf << 6));
    float sbin[4] = {0.0f, 0.0f, 0.0f, 0.0f};
#pragma unroll
    for (int q = 0; q < 16; ++q) {
        float4 v = xr[q];
        sbin[q >> 2] += (v.x + v.y) + (v.z + v.w);
    }
    int by = r >> 4;
#pragma unroll
    for (int t = 0; t < 4; ++t) atomicAdd(&pm[by * 8 + hf * 4 + t], sbin[t]);
    __syncthreads();

    if (tid < 64) {
        int byy = tid >> 3, bx = tid & 7;
        float pe = (c < 64) ? d_tabR[byy * 64 + c] : d_tabR[bx * 64 + (c - 64)];
        pm[tid] = (pm[tid] + 16.0f * pe) * (1.0f / 256.0f);
    }
    __syncthreads();

    if (tid < 16) {
        int i = tid >> 2, j = tid & 3;
        g4[tid] = 0.25f * (pm[(2 * i) * 8 + 2 * j] + pm[(2 * i) * 8 + 2 * j + 1] +
                           pm[(2 * i + 1) * 8 + 2 * j] + pm[(2 * i + 1) * 8 + 2 * j + 1]);
    } else if (tid < 20) {
        int t = tid - 16;
        int i = t >> 1, j = t & 1;
        float s = 0.0f;
        for (int yy = 0; yy < 4; ++yy)
            for (int xq = 0; xq < 4; ++xq) s += pm[(4 * i + yy) * 8 + 4 * j + xq];
        g2[t] = s * (1.0f / 16.0f);
    } else if (tid == 20) {
        float s = 0.0f;
        for (int q = 0; q < 64; ++q) s += pm[q];
        g1[0] = s * (1.0f / 64.0f);
    }
    __syncthreads();

    if (tid < KVL) {
        float wv[9];
#pragma unroll
        for (int q = 0; q < 9; ++q) wv[q] = dw[c * 9 + q];
        const float* g;
        int s, ly, lx;
        if (tid < 64)      { g = pm; s = 8; ly = tid >> 3;        lx = tid & 7; }
        else if (tid < 80) { int t = tid - 64; g = g4; s = 4; ly = t >> 2; lx = t & 3; }
        else if (tid < 84) { int t = tid - 80; g = g2; s = 2; ly = t >> 1; lx = t & 1; }
        else               { g = g1; s = 1; ly = 0; lx = 0; }
        float a = 0.0f;
#pragma unroll
        for (int ky = 0; ky < 3; ++ky) {
            int iy = ly + ky - 1;
            bool oky = (iy >= 0) && (iy < s);
#pragma unroll
            for (int kx = 0; kx < 3; ++kx) {
                int ix = lx + kx - 1;
                if (oky && ix >= 0 && ix < s) a += g[iy * s + ix] * wv[ky * 3 + kx];
            }
        }
        d_y1[((size_t)b * KVL + tid) * NC + c] = a;   // transposed store
    }
}

// ----------------------------------------------------------------------------
// K2: per-(b,row): pointwise 1x1 -> LayerNorm(c) -> exact GELU -> KV projection
// All weight reads coalesced via pre-transposed d_pwT / d_WkvT.
// ----------------------------------------------------------------------------
__global__ void k_pw_ln_kv(const float* __restrict__ lnw, const float* __restrict__ lnb) {
    __shared__ float ycol[128];
    __shared__ float part[256];
    __shared__ float zs[128];
    __shared__ float red[2];
    int tid = threadIdx.x;
    int b = blockIdx.x / KVL;
    int row = blockIdx.x - b * KVL;

    if (tid < 128) ycol[tid] = d_y1[((size_t)b * KVL + row) * NC + tid];
    __syncthreads();

    // pointwise: split ci-range over the two thread halves
    {
        int o = tid & 127;
        int half = tid >> 7;                 // 0: ci 0..63, 1: ci 64..127
        const float* wc = d_pwT + (half << 6) * 128 + o;
        const float* yc = ycol + (half << 6);
        float a = 0.0f;
#pragma unroll 8
        for (int ci = 0; ci < 64; ++ci) a += wc[ci * 128] * yc[ci];
        part[tid] = a;
    }
    __syncthreads();
    if (tid < 128) zs[tid] = part[tid] + part[tid + 128];
    __syncthreads();

    if (tid < 32) {
        float s = zs[tid] + zs[tid + 32] + zs[tid + 64] + zs[tid + 96];
#pragma unroll
        for (int o = 16; o; o >>= 1) s += __shfl_xor_sync(0xffffffffu, s, o);
        if (tid == 0) red[0] = s * (1.0f / 128.0f);
    }
    __syncthreads();
    float mu = red[0];
    if (tid < 32) {
        float s = 0.0f;
#pragma unroll
        for (int q = 0; q < 4; ++q) { float dd = zs[tid + 32 * q] - mu; s += dd * dd; }
#pragma unroll
        for (int o = 16; o; o >>= 1) s += __shfl_xor_sync(0xffffffffu, s, o);
        if (tid == 0) red[1] = s * (1.0f / 128.0f);
    }
    __syncthreads();
    float rstd = rsqrtf(red[1] + 1e-5f);
    if (tid < 128) {
        float zn = (zs[tid] - mu) * rstd * lnw[tid] + lnb[tid];
        zs[tid] = 0.5f * zn * (1.0f + erff(zn * 0.70710678118654752f));
    }
    __syncthreads();

    // KV projection: output o = tid (0..127 -> k, 128..255 -> v), coalesced W
    float a = 0.0f;
    const float* wc = d_WkvT + tid;
#pragma unroll 8
    for (int ci = 0; ci < 128; ++ci) a += wc[ci * 256] * zs[ci];
    int m = (tid >> 4) & 7, d = tid & 15;
    float* dst = (tid < 128) ? d_k : d_v;
    dst[((size_t)(b * NH + m) * KVL + row) * HD + d] = a;
}

// ----------------------------------------------------------------------------
// K3: fused main kernel: one block per (b, image row y), 512 threads.
// thread layout: th = tid>>6 (head / 16-channel tile), tx = tid&63 (2 pixels)
// ----------------------------------------------------------------------------
#define STR   132
#define SWZ(c) ((c) & 28)
#define OFF_B (128 * STR)              // 16896
#define OFF_K (OFF_B + 128 * STR)      // 33792
#define OFF_V (OFF_K + NH * KVS)       // 44672
#define SMEMF (OFF_V + NH * KVS)       // 55552 floats = 222208 bytes

// out[x][o] = sum_c A[c*STR+x] * B[c][o^swz(c)]; acc[op][xi] packs (o=2op,2op+1)
__device__ __forceinline__ void gemm128x2(const float* __restrict__ A,
                                          const float* __restrict__ B,
                                          int tx, int th, u64 acc[8][2]) {
#pragma unroll
    for (int op = 0; op < 8; ++op) { acc[op][0] = 0ull; acc[op][1] = 0ull; }
    const float* ap = A + tx * 2;
    int base = th * 16;
#pragma unroll 4
    for (int k = 0; k < 128; ++k) {
        float2 av = *(const float2*)(ap + k * STR);
        const float* brow = B + k * STR;
        int s = SWZ(k);
        ulonglong2 b01 = *(const ulonglong2*)(brow + ((base     ) ^ s));
        ulonglong2 b23 = *(const ulonglong2*)(brow + ((base +  4) ^ s));
        ulonglong2 b45 = *(const ulonglong2*)(brow + ((base +  8) ^ s));
        ulonglong2 b67 = *(const ulonglong2*)(brow + ((base + 12) ^ s));
        u64 a0 = splat2(av.x), a1 = splat2(av.y);
        u64 bb[8] = {b01.x, b01.y, b23.x, b23.y, b45.x, b45.y, b67.x, b67.y};
#pragma unroll
        for (int op = 0; op < 8; ++op) {
            acc[op][0] = fma2(bb[op], a0, acc[op][0]);
            acc[op][1] = fma2(bb[op], a1, acc[op][1]);
        }
    }
}

__device__ __forceinline__ void load_w_swz(const float* __restrict__ W, float* __restrict__ Bs,
                                           int tid) {
    const float4* w4 = (const float4*)W;
    for (int i = tid; i < 4096; i += 512) {
        int o = i >> 5, cq = (i & 31) * 4;
        float4 w = w4[i];
        int col = o ^ SWZ(cq);   // (cq+d)&28 == cq&28 for d<4
        Bs[(cq    ) * STR + col] = w.x;
        Bs[(cq + 1) * STR + col] = w.y;
        Bs[(cq + 2) * STR + col] = w.z;
        Bs[(cq + 3) * STR + col] = w.w;
    }
}

__global__ void __launch_bounds__(512, 1)
k_main(const float* __restrict__ x, const float* __restrict__ Wq,
       const float* __restrict__ Wproj, const float* __restrict__ bproj,
       float* __restrict__ out) {
    extern __shared__ float sm[];
    float* As = sm;                // Xp (channel-major) then O
    float* Bs = sm + OFF_B;        // Wq(sw) -> Wproj(sw)
    float* Ks = sm + OFF_K;
    float* Vs = sm + OFF_V;
    int tid = threadIdx.x;
    int b = blockIdx.x >> 7;
    int y = blockIdx.x & 127;

    {   // K/V for this batch
        const float4* kg = (const float4*)(d_k + (size_t)b * NH * KVS);
        const float4* vg = (const float4*)(d_v + (size_t)b * NH * KVS);
        float4* k4 = (float4*)Ks;
        float4* v4 = (float4*)Vs;
        for (int i = tid; i < NH * KVS / 4; i += 512) { k4[i] = kg[i]; v4[i] = vg[i]; }
    }
    {   // Xp row (x + posenc), channel-major As[c*STR + xx]
        const float4* xr = (const float4*)(x + (((size_t)b * NC) << 14) + (y << 7));
        for (int i = tid; i < 4096; i += 512) {
            int c = i >> 5, xq = i & 31;
            float4 v = xr[c * 4096 + xq];
            if (c < 64) {
                float pe = d_tab[y * 64 + c];
                v.x += pe; v.y += pe; v.z += pe; v.w += pe;
            } else {
                float4 p = ((const float4*)d_tabT)[(c - 64) * 32 + xq];
                v.x += p.x; v.y += p.y; v.z += p.z; v.w += p.w;
            }
            *(float4*)(As + c * STR + xq * 4) = v;
        }
    }
    load_w_swz(Wq, Bs, tid);
    __syncthreads();

    int tx = tid & 63, th = tid >> 6;
    u64 acc[8][2];

    // ---- Q-GEMM ----
    gemm128x2(As, Bs, tx, th, acc);

    // acc[op][p] already IS pack2(Q[c=2op], Q[c=2op+1]) for pixel 2tx+p.
    // Fold in the hd^-0.5 = 0.25 scale; no smem round-trip needed.
    u64 q0[8], q1[8];
    {
        u64 s4 = splat2(0.25f);
#pragma unroll
        for (int op = 0; op < 8; ++op) {
            q0[op] = mul2(acc[op][0], s4);
            q1[op] = mul2(acc[op][1], s4);
        }
    }

    const u64* kb = (const u64*)(Ks + th * KVS);
    const u64* vb = (const u64*)(Vs + th * KVS);
    float* Os = As;   // Xp is dead after the GEMM (this thread read all it needs)
    __syncthreads();  // everyone done reading As/Bs before Os overwrites As

    // ---- attention: both pixels share each K/V load ----
    u64 oa0[8], oa1[8];
#pragma unroll
    for (int i = 0; i < 8; ++i) { oa0[i] = 0ull; oa1[i] = 0ull; }
    float s0 = 0.0f, s1 = 0.0f;
#pragma unroll 2
    for (int j = 0; j < KVL; ++j) {
        const float* kf = (const float*)(kb + j * 8);
        ulonglong2 k01 = *(const ulonglong2*)(kf);
        ulonglong2 k23 = *(const ulonglong2*)(kf + 4);
        ulonglong2 k45 = *(const ulonglong2*)(kf + 8);
        ulonglong2 k67 = *(const ulonglong2*)(kf + 12);
        u64 d00 = mul2(q0[0], k01.x), d01 = mul2(q0[1], k01.y);
        u64 d10 = mul2(q1[0], k01.x), d11 = mul2(q1[1], k01.y);
        d00 = fma2(q0[2], k23.x, d00);  d01 = fma2(q0[3], k23.y, d01);
        d10 = fma2(q1[2], k23.x, d10);  d11 = fma2(q1[3], k23.y, d11);
        d00 = fma2(q0[4], k45.x, d00);  d01 = fma2(q0[5], k45.y, d01);
        d10 = fma2(q1[4], k45.x, d10);  d11 = fma2(q1[5], k45.y, d11);
        d00 = fma2(q0[6], k67.x, d00);  d01 = fma2(q0[7], k67.y, d01);
        d10 = fma2(q1[6], k67.x, d10);  d11 = fma2(q1[7], k67.y, d11);
        float a0, b0, c0, e0l, a1f, b1f, c1f, e1l;
        unpack2(d00, a0, b0); unpack2(d01, c0, e0l);
        unpack2(d10, a1f, b1f); unpack2(d11, c1f, e1l);
        float e0 = __expf((a0 + b0) + (c0 + e0l));
        float e1 = __expf((a1f + b1f) + (c1f + e1l));
        s0 += e0; s1 += e1;
        u64 p0 = splat2(e0), p1 = splat2(e1);
        const float* vf = (const float*)(vb + j * 8);
        ulonglong2 v01 = *(const ulonglong2*)(vf);
        ulonglong2 v23 = *(const ulonglong2*)(vf + 4);
        ulonglong2 v45 = *(const ulonglong2*)(vf + 8);
        ulonglong2 v67 = *(const ulonglong2*)(vf + 12);
        oa0[0] = fma2(p0, v01.x, oa0[0]);  oa1[0] = fma2(p1, v01.x, oa1[0]);
        oa0[1] = fma2(p0, v01.y, oa0[1]);  oa1[1] = fma2(p1, v01.y, oa1[1]);
        oa0[2] = fma2(p0, v23.x, oa0[2]);  oa1[2] = fma2(p1, v23.x, oa1[2]);
        oa0[3] = fma2(p0, v23.y, oa0[3]);  oa1[3] = fma2(p1, v23.y, oa1[3]);
        oa0[4] = fma2(p0, v45.x, oa0[4]);  oa1[4] = fma2(p1, v45.x, oa1[4]);
        oa0[5] = fma2(p0, v45.y, oa0[5]);  oa1[5] = fma2(p1, v45.y, oa1[5]);
        oa0[6] = fma2(p0, v67.x, oa0[6]);  oa1[6] = fma2(p1, v67.x, oa1[6]);
        oa0[7] = fma2(p0, v67.y, oa0[7]);  oa1[7] = fma2(p1, v67.y, oa1[7]);
    }
    {
        float i0 = 1.0f / s0, i1 = 1.0f / s1;
        int xx = tx * 2;
#pragma unroll
        for (int i = 0; i < 8; ++i) {
            float lo, hi;
            unpack2(oa0[i], lo, hi);
            Os[(th * 16 + 2 * i) * STR + xx] = lo * i0;
            Os[(th * 16 + 2 * i + 1) * STR + xx] = hi * i0;
            unpack2(oa1[i], lo, hi);
            Os[(th * 16 + 2 * i) * STR + xx + 1] = lo * i1;
            Os[(th * 16 + 2 * i + 1) * STR + xx + 1] = hi * i1;
        }
    }
    __syncthreads();   // Os complete; Bs (Wq) dead

    // ---- out-proj GEMM ----
    load_w_swz(Wproj, Bs, tid);
    __syncthreads();
    gemm128x2(Os, Bs, tx, th, acc);

    float* og = out + (((size_t)b * NC) << 14) + (y << 7) + tx * 2;
#pragma unroll
    for (int op = 0; op < 8; ++op) {
        float b0 = bproj[th * 16 + 2 * op];
        float b1 = bproj[th * 16 + 2 * op + 1];
        float l0, h0, l1, h1;
        unpack2(acc[op][0], l0, h0);   // pixel 2tx:   channels 2op, 2op+1
        unpack2(acc[op][1], l1, h1);   // pixel 2tx+1: channels 2op, 2op+1
        *(float2*)(og + ((size_t)(th * 16 + 2 * op) << 14)) = make_float2(l0 + b0, l1 + b0);
        *(float2*)(og + ((size_t)(th * 16 + 2 * op + 1) << 14)) = make_float2(h0 + b1, h1 + b1);
    }
}

// ----------------------------------------------------------------------------
extern "C" void kernel_launch(void* const* d_in, const int* in_sizes, int n_in,
                              void* d_out, int out_size) {
    const float* x     = (const float*)d_in[0];
    const float* Wq    = (const float*)d_in[1];
    const float* Wkv   = (const float*)d_in[2];
    const float* Wproj = (const float*)d_in[3];
    const float* bproj = (const float*)d_in[4];
    const float* dw    = (const float*)d_in[5];
    const float* pw    = (const float*)d_in[6];
    const float* lnw   = (const float*)d_in[7];
    const float* lnb   = (const float*)d_in[8];
    float* out = (float*)d_out;

    cudaFuncSetAttribute(k_main, cudaFuncAttributeMaxDynamicSharedMemorySize,
                         SMEMF * (int)sizeof(float));

    k_tables<<<258, 256>>>(pw, Wkv);
    k_pool_dw<<<NB * NC, 256>>>(x, dw);
    k_pw_ln_kv<<<NB * KVL, 256>>>(lnw, lnb);
    k_main<<<NB * 128, 512, SMEMF * sizeof(float)>>>(x, Wq, Wproj, bproj, out);
}

// round 9
// speedup vs baseline: 1.3285x; 1.3285x over previous
#include <cuda_runtime.h>
#include <cuda_bf16.h>
#include <math.h>
#include <stdint.h>

#define NB 8
#define NC 128
#define NH 8
#define HD 16
#define KVL 85
#define KVS (KVL * HD)

// bf16 tile geometry: 128 rows x 128 cols, row stride 136 bf16 = 272 bytes
// (272 % 16 == 0 -> every ldmatrix row address is 16B-aligned;
//  272 = 17*16B -> 8 consecutive rows hit 8 distinct 16B chunks: conflict-free)
#define TSTR 272
#define TILEB (128 * TSTR)   // 34816

__device__ __align__(16) float d_tab[128 * 64];
__device__ __align__(16) float d_tabT[64 * 128];
__device__ __align__(16) float d_tabR[8 * 64];
__device__ __align__(16) float d_y1[NB * KVL * NC];
__device__ __align__(16) float d_pwT[128 * 128];
__device__ __align__(16) float d_WkvT[128 * 256];
__device__ __align__(16) float d_k[NB * NH * KVS];
__device__ __align__(16) float d_v[NB * NH * KVS];
__device__ __align__(16) unsigned char d_wqh[TILEB];
__device__ __align__(16) unsigned char d_wql[TILEB];
__device__ __align__(16) unsigned char d_wph[TILEB];
__device__ __align__(16) unsigned char d_wpl[TILEB];

typedef unsigned long long u64;

__device__ __forceinline__ u64 fma2(u64 a, u64 b, u64 c) {
    u64 d; asm("fma.rn.f32x2 %0, %1, %2, %3;" : "=l"(d) : "l"(a), "l"(b), "l"(c)); return d;
}
__device__ __forceinline__ u64 mul2(u64 a, u64 b) {
    u64 d; asm("mul.rn.f32x2 %0, %1, %2;" : "=l"(d) : "l"(a), "l"(b)); return d;
}
__device__ __forceinline__ u64 splat2(float x) {
    u64 d; asm("mov.b64 %0, {%1, %1};" : "=l"(d) : "f"(x)); return d;
}
__device__ __forceinline__ u64 pack2(float lo, float hi) {
    u64 d; asm("mov.b64 %0, {%1, %2};" : "=l"(d) : "f"(lo), "f"(hi)); return d;
}
__device__ __forceinline__ void unpack2(u64 v, float& lo, float& hi) {
    asm("mov.b64 {%0, %1}, %2;" : "=f"(lo), "=f"(hi) : "l"(v));
}
__device__ __forceinline__ uint32_t bf2u(__nv_bfloat162 v) {
    return ((uint32_t)__bfloat16_as_ushort(v.y) << 16) | (uint32_t)__bfloat16_as_ushort(v.x);
}

// ---------------- K0: tables + transposes (validated R4) ----------------
__global__ void k_tables(const float* __restrict__ pw, const float* __restrict__ Wkv) {
    int idx = blockIdx.x * 256 + threadIdx.x;
    if (idx < 8192) {
        int yv = idx >> 6, j = idx & 63, i = j & 31;
        float inv = powf(10000.0f, -(2.0f * (float)i) / 64.0f);
        float a = (float)yv * inv;
        d_tab[idx] = (j < 32) ? sinf(a) : cosf(a);
    } else if (idx < 16384) {
        int e = idx - 8192;
        int j = e >> 7, p = e & 127, i = j & 31;
        float inv = powf(10000.0f, -(2.0f * (float)i) / 64.0f);
        float a = (float)p * inv;
        d_tabT[e] = (j < 32) ? sinf(a) : cosf(a);
    } else if (idx < 16896) {
        int e = idx - 16384;
        int bin = e >> 6, j = e & 63, i = j & 31;
        float inv = powf(10000.0f, -(2.0f * (float)i) / 64.0f);
        float s = 0.0f;
        for (int t = 0; t < 16; ++t) {
            float a = (float)(bin * 16 + t) * inv;
            s += (j < 32) ? sinf(a) : cosf(a);
        }
        d_tabR[e] = s;
    } else if (idx < 16896 + 16384) {
        int e = idx - 16896;
        d_pwT[e] = pw[(e & 127) * 128 + (e >> 7)];
    } else if (idx < 16896 + 16384 + 32768) {
        int e = idx - (16896 + 16384);
        d_WkvT[e] = Wkv[(e & 255) * 128 + (e >> 8)];
    }
}

// ---------------- K0b: bf16 hi/lo split of Wq/Wproj, 272B-stride tiles -----
__global__ void k_wsplit(const float* __restrict__ Wq, const float* __restrict__ Wp) {
    int i = blockIdx.x * 256 + threadIdx.x;
    if (i >= 32768) return;
    const float* W; unsigned char *H, *L; int e;
    if (i < 16384) { W = Wq; H = d_wqh; L = d_wql; e = i; }
    else           { W = Wp; H = d_wph; L = d_wpl; e = i - 16384; }
    int o = e >> 7, c = e & 127;
    float v = W[e];
    __nv_bfloat16 h = __float2bfloat16(v);
    float r = v - __bfloat162float(h);
    uint32_t off = (uint32_t)(o * TSTR + c * 2);
    *(__nv_bfloat16*)(H + off) = h;
    *(__nv_bfloat16*)(L + off) = __float2bfloat16(r);
}

// ---------------- K1: ASPP pooling + depthwise conv (validated R4) ---------
__global__ void k_pool_dw(const float* __restrict__ x, const float* __restrict__ dw) {
    __shared__ float pm[64];
    __shared__ float g4[16];
    __shared__ float g2[4];
    __shared__ float g1[1];
    int tid = threadIdx.x;
    int b = blockIdx.x >> 7, c = blockIdx.x & 127;
    if (tid < 64) pm[tid] = 0.0f;
    __syncthreads();
    int r = tid >> 1, hf = tid & 1;
    const float4* xr = (const float4*)(x + ((size_t)(b * NC + c) << 14) + (r << 7) + (hf << 6));
    float sbin[4] = {0.0f, 0.0f, 0.0f, 0.0f};
#pragma unroll
    for (int q = 0; q < 16; ++q) {
        float4 v = xr[q];
        sbin[q >> 2] += (v.x + v.y) + (v.z + v.w);
    }
    int by = r >> 4;
#pragma unroll
    for (int t = 0; t < 4; ++t) atomicAdd(&pm[by * 8 + hf * 4 + t], sbin[t]);
    __syncthreads();
    if (tid < 64) {
        int byy = tid >> 3, bx = tid & 7;
        float pe = (c < 64) ? d_tabR[byy * 64 + c] : d_tabR[bx * 64 + (c - 64)];
        pm[tid] = (pm[tid] + 16.0f * pe) * (1.0f / 256.0f);
    }
    __syncthreads();
    if (tid < 16) {
        int i = tid >> 2, j = tid & 3;
        g4[tid] = 0.25f * (pm[(2 * i) * 8 + 2 * j] + pm[(2 * i) * 8 + 2 * j + 1] +
                           pm[(2 * i + 1) * 8 + 2 * j] + pm[(2 * i + 1) * 8 + 2 * j + 1]);
    } else if (tid < 20) {
        int t = tid - 16, i = t >> 1, j = t & 1;
        float s = 0.0f;
        for (int yy = 0; yy < 4; ++yy)
            for (int xq = 0; xq < 4; ++xq) s += pm[(4 * i + yy) * 8 + 4 * j + xq];
        g2[t] = s * (1.0f / 16.0f);
    } else if (tid == 20) {
        float s = 0.0f;
        for (int q = 0; q < 64; ++q) s += pm[q];
        g1[0] = s * (1.0f / 64.0f);
    }
    __syncthreads();
    if (tid < KVL) {
        float wv[9];
#pragma unroll
        for (int q = 0; q < 9; ++q) wv[q] = dw[c * 9 + q];
        const float* g; int s, ly, lx;
        if (tid < 64)      { g = pm; s = 8; ly = tid >> 3;        lx = tid & 7; }
        else if (tid < 80) { int t = tid - 64; g = g4; s = 4; ly = t >> 2; lx = t & 3; }
        else if (tid < 84) { int t = tid - 80; g = g2; s = 2; ly = t >> 1; lx = t & 1; }
        else               { g = g1; s = 1; ly = 0; lx = 0; }
        float a = 0.0f;
#pragma unroll
        for (int ky = 0; ky < 3; ++ky) {
            int iy = ly + ky - 1;
            bool oky = (iy >= 0) && (iy < s);
#pragma unroll
            for (int kx = 0; kx < 3; ++kx) {
                int ix = lx + kx - 1;
                if (oky && ix >= 0 && ix < s) a += g[iy * s + ix] * wv[ky * 3 + kx];
            }
        }
        d_y1[((size_t)b * KVL + tid) * NC + c] = a;
    }
}

// ---------------- K2: pointwise -> LN -> GELU -> KV proj (validated R4) ----
__global__ void k_pw_ln_kv(const float* __restrict__ lnw, const float* __restrict__ lnb) {
    __shared__ float ycol[128];
    __shared__ float part[256];
    __shared__ float zs[128];
    __shared__ float red[2];
    int tid = threadIdx.x;
    int b = blockIdx.x / KVL;
    int row = blockIdx.x - b * KVL;
    if (tid < 128) ycol[tid] = d_y1[((size_t)b * KVL + row) * NC + tid];
    __syncthreads();
    {
        int o = tid & 127, half = tid >> 7;
        const float* wc = d_pwT + (half << 6) * 128 + o;
        const float* yc = ycol + (half << 6);
        float a = 0.0f;
#pragma unroll 8
        for (int ci = 0; ci < 64; ++ci) a += wc[ci * 128] * yc[ci];
        part[tid] = a;
    }
    __syncthreads();
    if (tid < 128) zs[tid] = part[tid] + part[tid + 128];
    __syncthreads();
    if (tid < 32) {
        float s = zs[tid] + zs[tid + 32] + zs[tid + 64] + zs[tid + 96];
#pragma unroll
        for (int o = 16; o; o >>= 1) s += __shfl_xor_sync(0xffffffffu, s, o);
        if (tid == 0) red[0] = s * (1.0f / 128.0f);
    }
    __syncthreads();
    float mu = red[0];
    if (tid < 32) {
        float s = 0.0f;
#pragma unroll
        for (int q = 0; q < 4; ++q) { float dd = zs[tid + 32 * q] - mu; s += dd * dd; }
#pragma unroll
        for (int o = 16; o; o >>= 1) s += __shfl_xor_sync(0xffffffffu, s, o);
        if (tid == 0) red[1] = s * (1.0f / 128.0f);
    }
    __syncthreads();
    float rstd = rsqrtf(red[1] + 1e-5f);
    if (tid < 128) {
        float zn = (zs[tid] - mu) * rstd * lnw[tid] + lnb[tid];
        zs[tid] = 0.5f * zn * (1.0f + erff(zn * 0.70710678118654752f));
    }
    __syncthreads();
    float a = 0.0f;
    const float* wc = d_WkvT + tid;
#pragma unroll 8
    for (int ci = 0; ci < 128; ++ci) a += wc[ci * 256] * zs[ci];
    int m = (tid >> 4) & 7, d = tid & 15;
    float* dst = (tid < 128) ? d_k : d_v;
    dst[((size_t)(b * NH + m) * KVL + row) * HD + d] = a;
}

// ---------------- K3: fused main (HMMA mma.sync projections) ----------------
#define OWH 0
#define OWL TILEB
#define OXH (2 * TILEB)
#define OXL (3 * TILEB)
#define OKS (4 * TILEB)
#define OVS (OKS + 43520)
#define OBI (OVS + 43520)
#define SMB (OBI + 512 + 16)

#define LDMX4(r0, r1, r2, r3, a) \
    asm volatile("ldmatrix.sync.aligned.m8n8.x4.shared.b16 {%0,%1,%2,%3}, [%4];" \
        : "=r"(r0), "=r"(r1), "=r"(r2), "=r"(r3) : "r"(a))
#define LDMX2(r0, r1, a) \
    asm volatile("ldmatrix.sync.aligned.m8n8.x2.shared.b16 {%0,%1}, [%2];" \
        : "=r"(r0), "=r"(r1) : "r"(a))
#define MMA16816(d, a0, a1, a2, a3, b0, b1) \
    asm volatile("mma.sync.aligned.m16n8k16.row.col.f32.bf16.bf16.f32 " \
        "{%0,%1,%2,%3}, {%4,%5,%6,%7}, {%8,%9}, {%0,%1,%2,%3};" \
        : "+f"((d)[0]), "+f"((d)[1]), "+f"((d)[2]), "+f"((d)[3]) \
        : "r"(a0), "r"(a1), "r"(a2), "r"(a3), "r"(b0), "r"(b1))

// D[c][p] = sum_k W[c][k] * X[p][k] with bf16 hi/lo 3-chain split.
// warp w: m-tile = w&7 (16 channels), n-tiles (w>>3)*8 .. +8 (64 pixels).
__device__ __forceinline__ void hmma_gemm(uint32_t sb, uint32_t aBase, uint32_t bBase,
                                          int w, int lane, float D[8][4]) {
#pragma unroll
    for (int n = 0; n < 8; ++n)
#pragma unroll
        for (int q = 0; q < 4; ++q) D[n][q] = 0.0f;
    int mt = w & 7, nw = w >> 3;
    int sub = lane >> 3, r = lane & 7;
    uint32_t aH = sb + aBase + (uint32_t)((mt * 16 + (sub & 1) * 8 + r) * TSTR + (sub >> 1) * 16);
    uint32_t aL = aH + TILEB;
    int bl = lane & 15;
    uint32_t bH = sb + bBase + (uint32_t)((nw * 64 + (bl & 7)) * TSTR + (bl >> 3) * 16);
    uint32_t bL = bH + TILEB;
#pragma unroll
    for (int kc = 0; kc < 8; ++kc) {
        uint32_t ah0, ah1, ah2, ah3, al0, al1, al2, al3;
        LDMX4(ah0, ah1, ah2, ah3, aH + kc * 32);
        LDMX4(al0, al1, al2, al3, aL + kc * 32);
#pragma unroll
        for (int n = 0; n < 8; ++n) {
            uint32_t bh0, bh1, bl0, bl1;
            LDMX2(bh0, bh1, bH + n * (8 * TSTR) + kc * 32);
            LDMX2(bl0, bl1, bL + n * (8 * TSTR) + kc * 32);
            MMA16816(D[n], ah0, ah1, ah2, ah3, bh0, bh1);
            MMA16816(D[n], al0, al1, al2, al3, bh0, bh1);
            MMA16816(D[n], ah0, ah1, ah2, ah3, bl0, bl1);
        }
    }
}

__global__ void __launch_bounds__(512, 1)
k_main(const float* __restrict__ x, const float* __restrict__ bproj,
       float* __restrict__ out) {
    extern __shared__ char smc[];
    uint32_t sb;
    asm("{ .reg .u64 t; cvta.to.shared.u64 t, %1; cvt.u32.u64 %0, t; }" : "=r"(sb) : "l"(smc));
    int tid = threadIdx.x, w = tid >> 5, lane = tid & 31;
    int b = blockIdx.x >> 7, y = blockIdx.x & 127;

    if (tid < 128) ((float*)(smc + OBI))[tid] = bproj[tid];
    {   // K/V
        const float4* kg = (const float4*)(d_k + (size_t)b * NH * KVS);
        const float4* vg = (const float4*)(d_v + (size_t)b * NH * KVS);
        float4* ks = (float4*)(smc + OKS);
        float4* vs = (float4*)(smc + OVS);
        for (int i = tid; i < NH * KVS / 4; i += 512) { ks[i] = kg[i]; vs[i] = vg[i]; }
    }
    {   // Wq bf16 tiles
        const float4* h4 = (const float4*)d_wqh;
        const float4* l4 = (const float4*)d_wql;
        float4* wh = (float4*)(smc + OWH);
        float4* wl = (float4*)(smc + OWL);
        for (int i = tid; i < TILEB / 16; i += 512) { wh[i] = h4[i]; wl[i] = l4[i]; }
    }
    {   // Xp bf16 split tiles: rows = pixels p, cols = channels c
        int p = tid & 127;
        int yoff = y << 7;
        for (int g = tid >> 7; g < 64; g += 4) {
            int c0 = g * 2, c1 = c0 + 1;
            float v0 = x[((size_t)(b * NC + c0) << 14) + yoff + p];
            float v1 = x[((size_t)(b * NC + c1) << 14) + yoff + p];
            v0 += (c0 < 64) ? d_tab[y * 64 + c0] : d_tabT[(c0 - 64) * 128 + p];
            v1 += (c1 < 64) ? d_tab[y * 64 + c1] : d_tabT[(c1 - 64) * 128 + p];
            __nv_bfloat162 hh = __floats2bfloat162_rn(v0, v1);
            __nv_bfloat162 ll = __floats2bfloat162_rn(v0 - __bfloat162float(hh.x),
                                                      v1 - __bfloat162float(hh.y));
            uint32_t off = (uint32_t)(p * TSTR + c0 * 2);
            *(uint32_t*)(smc + OXH + off) = bf2u(hh);
            *(uint32_t*)(smc + OXL + off) = bf2u(ll);
        }
    }
    __syncthreads();

    float D[8][4];
    // ---- Q-GEMM (HMMA) ----
    hmma_gemm(sb, OWH, OXH, w, lane, D);
    __syncthreads();   // all Wq/Xp reads done; OWH/OWL become Q fp32 [c][p]

    float* Qs = (float*)(smc + OWH);
    {
        int mt = w & 7, nw = w >> 3;
        int rc = mt * 16 + (lane >> 2);
#pragma unroll
        for (int n = 0; n < 8; ++n) {
            int p0 = nw * 64 + n * 8 + (lane & 3) * 2;
            *(float2*)&Qs[rc * 128 + p0] = make_float2(D[n][0] * 0.25f, D[n][1] * 0.25f);
            *(float2*)&Qs[(rc + 8) * 128 + p0] = make_float2(D[n][2] * 0.25f, D[n][3] * 0.25f);
        }
    }
    __syncthreads();

    // ---- load Q to regs: thread = (head th, pixels 2tx, 2tx+1) ----
    int th = tid >> 6, tx = tid & 63, xx = tx * 2;
    u64 q0[8], q1[8];
#pragma unroll
    for (int op = 0; op < 8; ++op) {
        int c = th * 16 + 2 * op;
        q0[op] = pack2(Qs[c * 128 + xx], Qs[(c + 1) * 128 + xx]);
        q1[op] = pack2(Qs[c * 128 + xx + 1], Qs[(c + 1) * 128 + xx + 1]);
    }
    __syncthreads();   // Q consumed; OWH/OWL free for Wproj

    {   // Wproj bf16 tiles
        const float4* h4 = (const float4*)d_wph;
        const float4* l4 = (const float4*)d_wpl;
        float4* wh = (float4*)(smc + OWH);
        float4* wl = (float4*)(smc + OWL);
        for (int i = tid; i < TILEB / 16; i += 512) { wh[i] = h4[i]; wl[i] = l4[i]; }
    }

    // ---- attention (validated R4 core) ----
    const u64* kb = (const u64*)((const float*)(smc + OKS) + th * KVS);
    const u64* vb = (const u64*)((const float*)(smc + OVS) + th * KVS);
    u64 oa0[8], oa1[8];
#pragma unroll
    for (int i = 0; i < 8; ++i) { oa0[i] = 0ull; oa1[i] = 0ull; }
    float s0 = 0.0f, s1 = 0.0f;
#pragma unroll 2
    for (int j = 0; j < KVL; ++j) {
        const float* kf = (const float*)(kb + j * 8);
        ulonglong2 k01 = *(const ulonglong2*)(kf);
        ulonglong2 k23 = *(const ulonglong2*)(kf + 4);
        ulonglong2 k45 = *(const ulonglong2*)(kf + 8);
        ulonglong2 k67 = *(const ulonglong2*)(kf + 12);
        u64 d00 = mul2(q0[0], k01.x), d01 = mul2(q0[1], k01.y);
        u64 d10 = mul2(q1[0], k01.x), d11 = mul2(q1[1], k01.y);
        d00 = fma2(q0[2], k23.x, d00);  d01 = fma2(q0[3], k23.y, d01);
        d10 = fma2(q1[2], k23.x, d10);  d11 = fma2(q1[3], k23.y, d11);
        d00 = fma2(q0[4], k45.x, d00);  d01 = fma2(q0[5], k45.y, d01);
        d10 = fma2(q1[4], k45.x, d10);  d11 = fma2(q1[5], k45.y, d11);
        d00 = fma2(q0[6], k67.x, d00);  d01 = fma2(q0[7], k67.y, d01);
        d10 = fma2(q1[6], k67.x, d10);  d11 = fma2(q1[7], k67.y, d11);
        float a0, b0, c0f, e0l, a1f, b1f, c1f, e1l;
        unpack2(d00, a0, b0); unpack2(d01, c0f, e0l);
        unpack2(d10, a1f, b1f); unpack2(d11, c1f, e1l);
        float e0 = __expf((a0 + b0) + (c0f + e0l));
        float e1 = __expf((a1f + b1f) + (c1f + e1l));
        s0 += e0; s1 += e1;
        u64 p0 = splat2(e0), p1 = splat2(e1);
        const float* vf = (const float*)(vb + j * 8);
        ulonglong2 v01 = *(const ulonglong2*)(vf);
        ulonglong2 v23 = *(const ulonglong2*)(vf + 4);
        ulonglong2 v45 = *(const ulonglong2*)(vf + 8);
        ulonglong2 v67 = *(const ulonglong2*)(vf + 12);
        oa0[0] = fma2(p0, v01.x, oa0[0]);  oa1[0] = fma2(p1, v01.x, oa1[0]);
        oa0[1] = fma2(p0, v01.y, oa0[1]);  oa1[1] = fma2(p1, v01.y, oa1[1]);
        oa0[2] = fma2(p0, v23.x, oa0[2]);  oa1[2] = fma2(p1, v23.x, oa1[2]);
        oa0[3] = fma2(p0, v23.y, oa0[3]);  oa1[3] = fma2(p1, v23.y, oa1[3]);
        oa0[4] = fma2(p0, v45.x, oa0[4]);  oa1[4] = fma2(p1, v45.x, oa1[4]);
        oa0[5] = fma2(p0, v45.y, oa0[5]);  oa1[5] = fma2(p1, v45.y, oa1[5]);
        oa0[6] = fma2(p0, v67.x, oa0[6]);  oa1[6] = fma2(p1, v67.x, oa1[6]);
        oa0[7] = fma2(p0, v67.y, oa0[7]);  oa1[7] = fma2(p1, v67.y, oa1[7]);
    }
    {   // O bf16-split into X tiles (rows = pixels, cols = channels)
        float i0 = 1.0f / s0, i1 = 1.0f / s1;
#pragma unroll
        for (int i = 0; i < 8; ++i) {
            int c0 = th * 16 + 2 * i;
            float lo, hi;
            unpack2(oa0[i], lo, hi);
            float g0 = lo * i0, g1 = hi * i0;
            __nv_bfloat162 hh = __floats2bfloat162_rn(g0, g1);
            __nv_bfloat162 ll = __floats2bfloat162_rn(g0 - __bfloat162float(hh.x),
                                                      g1 - __bfloat162float(hh.y));
            uint32_t off = (uint32_t)(xx * TSTR + c0 * 2);
            *(uint32_t*)(smc + OXH + off) = bf2u(hh);
            *(uint32_t*)(smc + OXL + off) = bf2u(ll);
            unpack2(oa1[i], lo, hi);
            g0 = lo * i1; g1 = hi * i1;
            hh = __floats2bfloat162_rn(g0, g1);
            ll = __floats2bfloat162_rn(g0 - __bfloat162float(hh.x),
                                       g1 - __bfloat162float(hh.y));
            off = (uint32_t)((xx + 1) * TSTR + c0 * 2);
            *(uint32_t*)(smc + OXH + off) = bf2u(hh);
            *(uint32_t*)(smc + OXL + off) = bf2u(ll);
        }
    }
    __syncthreads();   // O tiles + Wproj ready

    // ---- out-proj GEMM (HMMA) + bias + store ----
    hmma_gemm(sb, OWH, OXH, w, lane, D);
    {
        const float* bias = (const float*)(smc + OBI);
        int mt = w & 7, nw = w >> 3;
        int rc = mt * 16 + (lane >> 2);
        float b0 = bias[rc], b1 = bias[rc + 8];
        float* og = out + (((size_t)b * NC) << 14) + (y << 7);
#pragma unroll
        for (int n = 0; n < 8; ++n) {
            int p0 = nw * 64 + n * 8 + (lane & 3) * 2;
            *(float2*)(og + (((size_t)rc) << 14) + p0) =
                make_float2(D[n][0] + b0, D[n][1] + b0);
            *(float2*)(og + (((size_t)(rc + 8)) << 14) + p0) =
                make_float2(D[n][2] + b1, D[n][3] + b1);
        }
    }
}

// ----------------------------------------------------------------------------
extern "C" void kernel_launch(void* const* d_in, const int* in_sizes, int n_in,
                              void* d_out, int out_size) {
    const float* x     = (const float*)d_in[0];
    const float* Wq    = (const float*)d_in[1];
    const float* Wkv   = (const float*)d_in[2];
    const float* Wproj = (const float*)d_in[3];
    const float* bproj = (const float*)d_in[4];
    const float* dw    = (const float*)d_in[5];
    const float* pw    = (const float*)d_in[6];
    const float* lnw   = (const float*)d_in[7];
    const float* lnb   = (const float*)d_in[8];
    float* out = (float*)d_out;

    cudaFuncSetAttribute(k_main, cudaFuncAttributeMaxDynamicSharedMemorySize, SMB);

    k_tables<<<258, 256>>>(pw, Wkv);
    k_wsplit<<<128, 256>>>(Wq, Wproj);
    k_pool_dw<<<NB * NC, 256>>>(x, dw);
    k_pw_ln_kv<<<NB * KVL, 256>>>(lnw, lnb);
    k_main<<<NB * 128, 512, SMB>>>(x, bproj, out);
}

// round 10
// speedup vs baseline: 1.3440x; 1.0117x over previous
#include <cuda_runtime.h>
#include <cuda_bf16.h>
#include <math.h>
#include <stdint.h>

#define NB 8
#define NC 128
#define NH 8
#define HD 16
#define KVL 85
#define KVS (KVL * HD)

// bf16 tile geometry: 128 rows x 128 cols, row stride 136 bf16 = 272 bytes
// (272 % 16 == 0 -> every ldmatrix row address is 16B-aligned;
//  272 = 17*16B -> 8 consecutive rows hit 8 distinct 16B chunks: conflict-free)
#define TSTR 272
#define TILEB (128 * TSTR)   // 34816

__device__ __align__(16) float d_tab[128 * 64];
__device__ __align__(16) float d_tabT[64 * 128];
__device__ __align__(16) float d_tabR[8 * 64];
__device__ __align__(16) float d_y1[NB * KVL * NC];
__device__ __align__(16) float d_pwT[128 * 128];
__device__ __align__(16) float d_WkvT[128 * 256];
__device__ __align__(16) float d_k[NB * NH * KVS];
__device__ __align__(16) float d_v[NB * NH * KVS];
__device__ __align__(16) unsigned char d_wqh[TILEB];
__device__ __align__(16) unsigned char d_wql[TILEB];
__device__ __align__(16) unsigned char d_wph[TILEB];
__device__ __align__(16) unsigned char d_wpl[TILEB];

typedef unsigned long long u64;

__device__ __forceinline__ u64 fma2(u64 a, u64 b, u64 c) {
    u64 d; asm("fma.rn.f32x2 %0, %1, %2, %3;" : "=l"(d) : "l"(a), "l"(b), "l"(c)); return d;
}
__device__ __forceinline__ u64 mul2(u64 a, u64 b) {
    u64 d; asm("mul.rn.f32x2 %0, %1, %2;" : "=l"(d) : "l"(a), "l"(b)); return d;
}
__device__ __forceinline__ u64 splat2(float x) {
    u64 d; asm("mov.b64 %0, {%1, %1};" : "=l"(d) : "f"(x)); return d;
}
__device__ __forceinline__ u64 pack2(float lo, float hi) {
    u64 d; asm("mov.b64 %0, {%1, %2};" : "=l"(d) : "f"(lo), "f"(hi)); return d;
}
__device__ __forceinline__ void unpack2(u64 v, float& lo, float& hi) {
    asm("mov.b64 {%0, %1}, %2;" : "=f"(lo), "=f"(hi) : "l"(v));
}
__device__ __forceinline__ uint32_t bf2u(__nv_bfloat162 v) {
    return ((uint32_t)__bfloat16_as_ushort(v.y) << 16) | (uint32_t)__bfloat16_as_ushort(v.x);
}

// ---------------- K0: tables + transposes + bf16 weight split (merged) ------
// idx ranges: [0,8192) d_tab, [8192,16384) d_tabT, [16384,16896) d_tabR,
// [16896,33280) d_pwT, [33280,66048) d_WkvT, [66048,98816) wsplit.
__global__ void k_prep(const float* __restrict__ pw, const float* __restrict__ Wkv,
                       const float* __restrict__ Wq, const float* __restrict__ Wp) {
    int idx = blockIdx.x * 256 + threadIdx.x;
    if (idx < 8192) {
        int yv = idx >> 6, j = idx & 63, i = j & 31;
        float inv = powf(10000.0f, -(2.0f * (float)i) / 64.0f);
        float a = (float)yv * inv;
        d_tab[idx] = (j < 32) ? sinf(a) : cosf(a);
    } else if (idx < 16384) {
        int e = idx - 8192;
        int j = e >> 7, p = e & 127, i = j & 31;
        float inv = powf(10000.0f, -(2.0f * (float)i) / 64.0f);
        float a = (float)p * inv;
        d_tabT[e] = (j < 32) ? sinf(a) : cosf(a);
    } else if (idx < 16896) {
        int e = idx - 16384;
        int bin = e >> 6, j = e & 63, i = j & 31;
        float inv = powf(10000.0f, -(2.0f * (float)i) / 64.0f);
        float s = 0.0f;
        for (int t = 0; t < 16; ++t) {
            float a = (float)(bin * 16 + t) * inv;
            s += (j < 32) ? sinf(a) : cosf(a);
        }
        d_tabR[e] = s;
    } else if (idx < 16896 + 16384) {
        int e = idx - 16896;
        d_pwT[e] = pw[(e & 127) * 128 + (e >> 7)];
    } else if (idx < 16896 + 16384 + 32768) {
        int e = idx - (16896 + 16384);
        d_WkvT[e] = Wkv[(e & 255) * 128 + (e >> 8)];
    } else if (idx < 66048 + 32768) {
        int i = idx - 66048;
        const float* W; unsigned char *H, *L; int e;
        if (i < 16384) { W = Wq; H = d_wqh; L = d_wql; e = i; }
        else           { W = Wp; H = d_wph; L = d_wpl; e = i - 16384; }
        int o = e >> 7, c = e & 127;
        float v = W[e];
        __nv_bfloat16 h = __float2bfloat16(v);
        float r = v - __bfloat162float(h);
        uint32_t off = (uint32_t)(o * TSTR + c * 2);
        *(__nv_bfloat16*)(H + off) = h;
        *(__nv_bfloat16*)(L + off) = __float2bfloat16(r);
    }
}

// ---------------- K1: ASPP pooling + depthwise conv (validated) -------------
__global__ void k_pool_dw(const float* __restrict__ x, const float* __restrict__ dw) {
    __shared__ float pm[64];
    __shared__ float g4[16];
    __shared__ float g2[4];
    __shared__ float g1[1];
    int tid = threadIdx.x;
    int b = blockIdx.x >> 7, c = blockIdx.x & 127;
    if (tid < 64) pm[tid] = 0.0f;
    __syncthreads();
    int r = tid >> 1, hf = tid & 1;
    const float4* xr = (const float4*)(x + ((size_t)(b * NC + c) << 14) + (r << 7) + (hf << 6));
    float sbin[4] = {0.0f, 0.0f, 0.0f, 0.0f};
#pragma unroll
    for (int q = 0; q < 16; ++q) {
        float4 v = xr[q];
        sbin[q >> 2] += (v.x + v.y) + (v.z + v.w);
    }
    int by = r >> 4;
#pragma unroll
    for (int t = 0; t < 4; ++t) atomicAdd(&pm[by * 8 + hf * 4 + t], sbin[t]);
    __syncthreads();
    if (tid < 64) {
        int byy = tid >> 3, bx = tid & 7;
        float pe = (c < 64) ? d_tabR[byy * 64 + c] : d_tabR[bx * 64 + (c - 64)];
        pm[tid] = (pm[tid] + 16.0f * pe) * (1.0f / 256.0f);
    }
    __syncthreads();
    if (tid < 16) {
        int i = tid >> 2, j = tid & 3;
        g4[tid] = 0.25f * (pm[(2 * i) * 8 + 2 * j] + pm[(2 * i) * 8 + 2 * j + 1] +
                           pm[(2 * i + 1) * 8 + 2 * j] + pm[(2 * i + 1) * 8 + 2 * j + 1]);
    } else if (tid < 20) {
        int t = tid - 16, i = t >> 1, j = t & 1;
        float s = 0.0f;
        for (int yy = 0; yy < 4; ++yy)
            for (int xq = 0; xq < 4; ++xq) s += pm[(4 * i + yy) * 8 + 4 * j + xq];
        g2[t] = s * (1.0f / 16.0f);
    } else if (tid == 20) {
        float s = 0.0f;
        for (int q = 0; q < 64; ++q) s += pm[q];
        g1[0] = s * (1.0f / 64.0f);
    }
    __syncthreads();
    if (tid < KVL) {
        float wv[9];
#pragma unroll
        for (int q = 0; q < 9; ++q) wv[q] = dw[c * 9 + q];
        const float* g; int s, ly, lx;
        if (tid < 64)      { g = pm; s = 8; ly = tid >> 3;        lx = tid & 7; }
        else if (tid < 80) { int t = tid - 64; g = g4; s = 4; ly = t >> 2; lx = t & 3; }
        else if (tid < 84) { int t = tid - 80; g = g2; s = 2; ly = t >> 1; lx = t & 1; }
        else               { g = g1; s = 1; ly = 0; lx = 0; }
        float a = 0.0f;
#pragma unroll
        for (int ky = 0; ky < 3; ++ky) {
            int iy = ly + ky - 1;
            bool oky = (iy >= 0) && (iy < s);
#pragma unroll
            for (int kx = 0; kx < 3; ++kx) {
                int ix = lx + kx - 1;
                if (oky && ix >= 0 && ix < s) a += g[iy * s + ix] * wv[ky * 3 + kx];
            }
        }
        d_y1[((size_t)b * KVL + tid) * NC + c] = a;
    }
}

// ---------------- K2: pointwise -> LN -> GELU -> KV proj (validated) --------
__global__ void k_pw_ln_kv(const float* __restrict__ lnw, const float* __restrict__ lnb) {
    __shared__ float ycol[128];
    __shared__ float part[256];
    __shared__ float zs[128];
    __shared__ float red[2];
    int tid = threadIdx.x;
    int b = blockIdx.x / KVL;
    int row = blockIdx.x - b * KVL;
    if (tid < 128) ycol[tid] = d_y1[((size_t)b * KVL + row) * NC + tid];
    __syncthreads();
    {
        int o = tid & 127, half = tid >> 7;
        const float* wc = d_pwT + (half << 6) * 128 + o;
        const float* yc = ycol + (half << 6);
        float a = 0.0f;
#pragma unroll 8
        for (int ci = 0; ci < 64; ++ci) a += wc[ci * 128] * yc[ci];
        part[tid] = a;
    }
    __syncthreads();
    if (tid < 128) zs[tid] = part[tid] + part[tid + 128];
    __syncthreads();
    if (tid < 32) {
        float s = zs[tid] + zs[tid + 32] + zs[tid + 64] + zs[tid + 96];
#pragma unroll
        for (int o = 16; o; o >>= 1) s += __shfl_xor_sync(0xffffffffu, s, o);
        if (tid == 0) red[0] = s * (1.0f / 128.0f);
    }
    __syncthreads();
    float mu = red[0];
    if (tid < 32) {
        float s = 0.0f;
#pragma unroll
        for (int q = 0; q < 4; ++q) { float dd = zs[tid + 32 * q] - mu; s += dd * dd; }
#pragma unroll
        for (int o = 16; o; o >>= 1) s += __shfl_xor_sync(0xffffffffu, s, o);
        if (tid == 0) red[1] = s * (1.0f / 128.0f);
    }
    __syncthreads();
    float rstd = rsqrtf(red[1] + 1e-5f);
    if (tid < 128) {
        float zn = (zs[tid] - mu) * rstd * lnw[tid] + lnb[tid];
        zs[tid] = 0.5f * zn * (1.0f + erff(zn * 0.70710678118654752f));
    }
    __syncthreads();
    float a = 0.0f;
    const float* wc = d_WkvT + tid;
#pragma unroll 8
    for (int ci = 0; ci < 128; ++ci) a += wc[ci * 256] * zs[ci];
    int m = (tid >> 4) & 7, d = tid & 15;
    float* dst = (tid < 128) ? d_k : d_v;
    dst[((size_t)(b * NH + m) * KVL + row) * HD + d] = a;
}

// ---------------- K3: fused main (HMMA mma.sync projections) ----------------
#define OWH 0
#define OWL TILEB
#define OXH (2 * TILEB)
#define OXL (3 * TILEB)
#define OKS (4 * TILEB)
#define OVS (OKS + 43520)
#define OBI (OVS + 43520)
#define SMB (OBI + 512 + 16)

#define LDMX4(r0, r1, r2, r3, a) \
    asm volatile("ldmatrix.sync.aligned.m8n8.x4.shared.b16 {%0,%1,%2,%3}, [%4];" \
        : "=r"(r0), "=r"(r1), "=r"(r2), "=r"(r3) : "r"(a))
#define LDMX2(r0, r1, a) \
    asm volatile("ldmatrix.sync.aligned.m8n8.x2.shared.b16 {%0,%1}, [%2];" \
        : "=r"(r0), "=r"(r1) : "r"(a))
#define MMA16816(d, a0, a1, a2, a3, b0, b1) \
    asm volatile("mma.sync.aligned.m16n8k16.row.col.f32.bf16.bf16.f32 " \
        "{%0,%1,%2,%3}, {%4,%5,%6,%7}, {%8,%9}, {%0,%1,%2,%3};" \
        : "+f"((d)[0]), "+f"((d)[1]), "+f"((d)[2]), "+f"((d)[3]) \
        : "r"(a0), "r"(a1), "r"(a2), "r"(a3), "r"(b0), "r"(b1))

// D[c][p] = sum_k W[c][k] * X[p][k] with bf16 hi/lo 3-chain split.
// warp w: m-tile = w&7 (16 channels), n-tiles (w>>3)*8 .. +8 (64 pixels).
__device__ __forceinline__ void hmma_gemm(uint32_t sb, uint32_t aBase, uint32_t bBase,
                                          int w, int lane, float D[8][4]) {
#pragma unroll
    for (int n = 0; n < 8; ++n)
#pragma unroll
        for (int q = 0; q < 4; ++q) D[n][q] = 0.0f;
    int mt = w & 7, nw = w >> 3;
    int sub = lane >> 3, r = lane & 7;
    uint32_t aH = sb + aBase + (uint32_t)((mt * 16 + (sub & 1) * 8 + r) * TSTR + (sub >> 1) * 16);
    uint32_t aL = aH + TILEB;
    int bl = lane & 15;
    uint32_t bH = sb + bBase + (uint32_t)((nw * 64 + (bl & 7)) * TSTR + (bl >> 3) * 16);
    uint32_t bL = bH + TILEB;
#pragma unroll
    for (int kc = 0; kc < 8; ++kc) {
        uint32_t ah0, ah1, ah2, ah3, al0, al1, al2, al3;
        LDMX4(ah0, ah1, ah2, ah3, aH + kc * 32);
        LDMX4(al0, al1, al2, al3, aL + kc * 32);
#pragma unroll
        for (int n = 0; n < 8; ++n) {
            uint32_t bh0, bh1, bl0, bl1;
            LDMX2(bh0, bh1, bH + n * (8 * TSTR) + kc * 32);
            LDMX2(bl0, bl1, bL + n * (8 * TSTR) + kc * 32);
            MMA16816(D[n], ah0, ah1, ah2, ah3, bh0, bh1);
            MMA16816(D[n], al0, al1, al2, al3, bh0, bh1);
            MMA16816(D[n], ah0, ah1, ah2, ah3, bl0, bl1);
        }
    }
}

__global__ void __launch_bounds__(512, 1)
k_main(const float* __restrict__ x, const float* __restrict__ bproj,
       float* __restrict__ out) {
    extern __shared__ char smc[];
    uint32_t sb;
    asm("{ .reg .u64 t; cvta.to.shared.u64 t, %1; cvt.u32.u64 %0, t; }" : "=r"(sb) : "l"(smc));
    int tid = threadIdx.x, w = tid >> 5, lane = tid & 31;
    int b = blockIdx.x >> 7, y = blockIdx.x & 127;

    if (tid < 128) ((float*)(smc + OBI))[tid] = bproj[tid];
    {   // K/V
        const float4* kg = (const float4*)(d_k + (size_t)b * NH * KVS);
        const float4* vg = (const float4*)(d_v + (size_t)b * NH * KVS);
        float4* ks = (float4*)(smc + OKS);
        float4* vs = (float4*)(smc + OVS);
        for (int i = tid; i < NH * KVS / 4; i += 512) { ks[i] = kg[i]; vs[i] = vg[i]; }
    }
    {   // Wq bf16 tiles
        const float4* h4 = (const float4*)d_wqh;
        const float4* l4 = (const float4*)d_wql;
        float4* wh = (float4*)(smc + OWH);
        float4* wl = (float4*)(smc + OWL);
        for (int i = tid; i < TILEB / 16; i += 512) { wh[i] = h4[i]; wl[i] = l4[i]; }
    }
    {   // Xp bf16 split tiles: rows = pixels p, cols = channels c
        int p = tid & 127;
        int yoff = y << 7;
        for (int g = tid >> 7; g < 64; g += 4) {
            int c0 = g * 2, c1 = c0 + 1;
            float v0 = x[((size_t)(b * NC + c0) << 14) + yoff + p];
            float v1 = x[((size_t)(b * NC + c1) << 14) + yoff + p];
            v0 += (c0 < 64) ? d_tab[y * 64 + c0] : d_tabT[(c0 - 64) * 128 + p];
            v1 += (c1 < 64) ? d_tab[y * 64 + c1] : d_tabT[(c1 - 64) * 128 + p];
            __nv_bfloat162 hh = __floats2bfloat162_rn(v0, v1);
            __nv_bfloat162 ll = __floats2bfloat162_rn(v0 - __bfloat162float(hh.x),
                                                      v1 - __bfloat162float(hh.y));
            uint32_t off = (uint32_t)(p * TSTR + c0 * 2);
            *(uint32_t*)(smc + OXH + off) = bf2u(hh);
            *(uint32_t*)(smc + OXL + off) = bf2u(ll);
        }
    }
    __syncthreads();

    float D[8][4];
    // ---- Q-GEMM (HMMA) ----
    hmma_gemm(sb, OWH, OXH, w, lane, D);
    __syncthreads();   // all Wq/Xp reads done; OWH/OWL become Q fp32 [c][p]

    float* Qs = (float*)(smc + OWH);
    {
        int mt = w & 7, nw = w >> 3;
        int rc = mt * 16 + (lane >> 2);
#pragma unroll
        for (int n = 0; n < 8; ++n) {
            int p0 = nw * 64 + n * 8 + (lane & 3) * 2;
            *(float2*)&Qs[rc * 128 + p0] = make_float2(D[n][0] * 0.25f, D[n][1] * 0.25f);
            *(float2*)&Qs[(rc + 8) * 128 + p0] = make_float2(D[n][2] * 0.25f, D[n][3] * 0.25f);
        }
    }
    __syncthreads();

    // ---- load Q to regs: thread = (head th, pixels 2tx, 2tx+1) ----
    int th = tid >> 6, tx = tid & 63, xx = tx * 2;
    u64 q0[8], q1[8];
#pragma unroll
    for (int op = 0; op < 8; ++op) {
        int c = th * 16 + 2 * op;
        q0[op] = pack2(Qs[c * 128 + xx], Qs[(c + 1) * 128 + xx]);
        q1[op] = pack2(Qs[c * 128 + xx + 1], Qs[(c + 1) * 128 + xx + 1]);
    }
    __syncthreads();   // Q consumed; OWH/OWL free for Wproj

    {   // Wproj bf16 tiles
        const float4* h4 = (const float4*)d_wph;
        const float4* l4 = (const float4*)d_wpl;
        float4* wh = (float4*)(smc + OWH);
        float4* wl = (float4*)(smc + OWL);
        for (int i = tid; i < TILEB / 16; i += 512) { wh[i] = h4[i]; wl[i] = l4[i]; }
    }

    // ---- attention (validated fp32 core) ----
    const u64* kb = (const u64*)((const float*)(smc + OKS) + th * KVS);
    const u64* vb = (const u64*)((const float*)(smc + OVS) + th * KVS);
    u64 oa0[8], oa1[8];
#pragma unroll
    for (int i = 0; i < 8; ++i) { oa0[i] = 0ull; oa1[i] = 0ull; }
    float s0 = 0.0f, s1 = 0.0f;
#pragma unroll 2
    for (int j = 0; j < KVL; ++j) {
        const float* kf = (const float*)(kb + j * 8);
        ulonglong2 k01 = *(const ulonglong2*)(kf);
        ulonglong2 k23 = *(const ulonglong2*)(kf + 4);
        ulonglong2 k45 = *(const ulonglong2*)(kf + 8);
        ulonglong2 k67 = *(const ulonglong2*)(kf + 12);
        u64 d00 = mul2(q0[0], k01.x), d01 = mul2(q0[1], k01.y);
        u64 d10 = mul2(q1[0], k01.x), d11 = mul2(q1[1], k01.y);
        d00 = fma2(q0[2], k23.x, d00);  d01 = fma2(q0[3], k23.y, d01);
        d10 = fma2(q1[2], k23.x, d10);  d11 = fma2(q1[3], k23.y, d11);
        d00 = fma2(q0[4], k45.x, d00);  d01 = fma2(q0[5], k45.y, d01);
        d10 = fma2(q1[4], k45.x, d10);  d11 = fma2(q1[5], k45.y, d11);
        d00 = fma2(q0[6], k67.x, d00);  d01 = fma2(q0[7], k67.y, d01);
        d10 = fma2(q1[6], k67.x, d10);  d11 = fma2(q1[7], k67.y, d11);
        float a0, b0, c0f, e0l, a1f, b1f, c1f, e1l;
        unpack2(d00, a0, b0); unpack2(d01, c0f, e0l);
        unpack2(d10, a1f, b1f); unpack2(d11, c1f, e1l);
        float e0 = __expf((a0 + b0) + (c0f + e0l));
        float e1 = __expf((a1f + b1f) + (c1f + e1l));
        s0 += e0; s1 += e1;
        u64 p0 = splat2(e0), p1 = splat2(e1);
        const float* vf = (const float*)(vb + j * 8);
        ulonglong2 v01 = *(const ulonglong2*)(vf);
        ulonglong2 v23 = *(const ulonglong2*)(vf + 4);
        ulonglong2 v45 = *(const ulonglong2*)(vf + 8);
        ulonglong2 v67 = *(const ulonglong2*)(vf + 12);
        oa0[0] = fma2(p0, v01.x, oa0[0]);  oa1[0] = fma2(p1, v01.x, oa1[0]);
        oa0[1] = fma2(p0, v01.y, oa0[1]);  oa1[1] = fma2(p1, v01.y, oa1[1]);
        oa0[2] = fma2(p0, v23.x, oa0[2]);  oa1[2] = fma2(p1, v23.x, oa1[2]);
        oa0[3] = fma2(p0, v23.y, oa0[3]);  oa1[3] = fma2(p1, v23.y, oa1[3]);
        oa0[4] = fma2(p0, v45.x, oa0[4]);  oa1[4] = fma2(p1, v45.x, oa1[4]);
        oa0[5] = fma2(p0, v45.y, oa0[5]);  oa1[5] = fma2(p1, v45.y, oa1[5]);
        oa0[6] = fma2(p0, v67.x, oa0[6]);  oa1[6] = fma2(p1, v67.x, oa1[6]);
        oa0[7] = fma2(p0, v67.y, oa0[7]);  oa1[7] = fma2(p1, v67.y, oa1[7]);
    }
    {   // O bf16-split into X tiles (rows = pixels, cols = channels)
        float i0 = 1.0f / s0, i1 = 1.0f / s1;
#pragma unroll
        for (int i = 0; i < 8; ++i) {
            int c0 = th * 16 + 2 * i;
            float lo, hi;
            unpack2(oa0[i], lo, hi);
            float g0 = lo * i0, g1 = hi * i0;
            __nv_bfloat162 hh = __floats2bfloat162_rn(g0, g1);
            __nv_bfloat162 ll = __floats2bfloat162_rn(g0 - __bfloat162float(hh.x),
                                                      g1 - __bfloat162float(hh.y));
            uint32_t off = (uint32_t)(xx * TSTR + c0 * 2);
            *(uint32_t*)(smc + OXH + off) = bf2u(hh);
            *(uint32_t*)(smc + OXL + off) = bf2u(ll);
            unpack2(oa1[i], lo, hi);
            g0 = lo * i1; g1 = hi * i1;
            hh = __floats2bfloat162_rn(g0, g1);
            ll = __floats2bfloat162_rn(g0 - __bfloat162float(hh.x),
                                       g1 - __bfloat162float(hh.y));
            off = (uint32_t)((xx + 1) * TSTR + c0 * 2);
            *(uint32_t*)(smc + OXH + off) = bf2u(hh);
            *(uint32_t*)(smc + OXL + off) = bf2u(ll);
        }
    }
    __syncthreads();   // O tiles + Wproj ready

    // ---- out-proj GEMM (HMMA) + bias + store ----
    hmma_gemm(sb, OWH, OXH, w, lane, D);
    {
        const float* bias = (const float*)(smc + OBI);
        int mt = w & 7, nw = w >> 3;
        int rc = mt * 16 + (lane >> 2);
        float b0 = bias[rc], b1 = bias[rc + 8];
        float* og = out + (((size_t)b * NC) << 14) + (y << 7);
#pragma unroll
        for (int n = 0; n < 8; ++n) {
            int p0 = nw * 64 + n * 8 + (lane & 3) * 2;
            *(float2*)(og + (((size_t)rc) << 14) + p0) =
                make_float2(D[n][0] + b0, D[n][1] + b0);
            *(float2*)(og + (((size_t)(rc + 8)) << 14) + p0) =
                make_float2(D[n][2] + b1, D[n][3] + b1);
        }
    }
}

// ----------------------------------------------------------------------------
extern "C" void kernel_launch(void* const* d_in, const int* in_sizes, int n_in,
                              void* d_out, int out_size) {
    const float* x     = (const float*)d_in[0];
    const float* Wq    = (const float*)d_in[1];
    const float* Wkv   = (const float*)d_in[2];
    const float* Wproj = (const float*)d_in[3];
    const float* bproj = (const float*)d_in[4];
    const float* dw    = (const float*)d_in[5];
    const float* pw    = (const float*)d_in[6];
    const float* lnw   = (const float*)d_in[7];
    const float* lnb   = (const float*)d_in[8];
    float* out = (float*)d_out;

    cudaFuncSetAttribute(k_main, cudaFuncAttributeMaxDynamicSharedMemorySize, SMB);

    k_prep<<<386, 256>>>(pw, Wkv, Wq, Wproj);
    k_pool_dw<<<NB * NC, 256>>>(x, dw);
    k_pw_ln_kv<<<NB * KVL, 256>>>(lnw, lnb);
    k_main<<<NB * 128, 512, SMB>>>(x, bproj, out);
}

// round 11
// speedup vs baseline: 1.3541x; 1.0075x over previous
#include <cuda_runtime.h>
#include <cuda_bf16.h>
#include <math.h>
#include <stdint.h>

#define NB 8
#define NC 128
#define NH 8
#define HD 16
#define KVL 85
#define KVS (KVL * HD)

// bf16 tile: 128 rows x 128 cols, row stride 136 bf16 = 272 B (16B-aligned rows,
// 272 = 17*16B -> 8 consecutive rows hit 8 distinct 16B chunks: conflict-free)
#define TSTR 272
#define TILEB (128 * TSTR)   // 34816

__device__ __align__(16) float d_tab[128 * 64];
__device__ __align__(16) float d_tabT[64 * 128];
__device__ __align__(16) float d_tabR[8 * 64];
__device__ __align__(16) float d_y1[NB * KVL * NC];
__device__ __align__(16) float d_pwT[128 * 128];
__device__ __align__(16) float d_WkvT[128 * 256];
__device__ __align__(16) float d_k[NB * NH * KVS];
__device__ __align__(16) float d_v[NB * NH * KVS];
__device__ __align__(16) unsigned char d_wqh[TILEB];
__device__ __align__(16) unsigned char d_wql[TILEB];
__device__ __align__(16) unsigned char d_wph[TILEB];
__device__ __align__(16) unsigned char d_wpl[TILEB];

typedef unsigned long long u64;

__device__ __forceinline__ u64 fma2(u64 a, u64 b, u64 c) {
    u64 d; asm("fma.rn.f32x2 %0, %1, %2, %3;" : "=l"(d) : "l"(a), "l"(b), "l"(c)); return d;
}
__device__ __forceinline__ u64 mul2(u64 a, u64 b) {
    u64 d; asm("mul.rn.f32x2 %0, %1, %2;" : "=l"(d) : "l"(a), "l"(b)); return d;
}
__device__ __forceinline__ u64 splat2(float x) {
    u64 d; asm("mov.b64 %0, {%1, %1};" : "=l"(d) : "f"(x)); return d;
}
__device__ __forceinline__ u64 pack2(float lo, float hi) {
    u64 d; asm("mov.b64 %0, {%1, %2};" : "=l"(d) : "f"(lo), "f"(hi)); return d;
}
__device__ __forceinline__ void unpack2(u64 v, float& lo, float& hi) {
    asm("mov.b64 {%0, %1}, %2;" : "=f"(lo), "=f"(hi) : "l"(v));
}
__device__ __forceinline__ uint32_t bf2u(__nv_bfloat162 v) {
    return ((uint32_t)__bfloat16_as_ushort(v.y) << 16) | (uint32_t)__bfloat16_as_ushort(v.x);
}

// ---------------- K0: tables + transposes + bf16 weight split (merged) ------
__global__ void k_prep(const float* __restrict__ pw, const float* __restrict__ Wkv,
                       const float* __restrict__ Wq, const float* __restrict__ Wp) {
    int idx = blockIdx.x * 256 + threadIdx.x;
    if (idx < 8192) {
        int yv = idx >> 6, j = idx & 63, i = j & 31;
        float inv = powf(10000.0f, -(2.0f * (float)i) / 64.0f);
        float a = (float)yv * inv;
        d_tab[idx] = (j < 32) ? sinf(a) : cosf(a);
    } else if (idx < 16384) {
        int e = idx - 8192;
        int j = e >> 7, p = e & 127, i = j & 31;
        float inv = powf(10000.0f, -(2.0f * (float)i) / 64.0f);
        float a = (float)p * inv;
        d_tabT[e] = (j < 32) ? sinf(a) : cosf(a);
    } else if (idx < 16896) {
        int e = idx - 16384;
        int bin = e >> 6, j = e & 63, i = j & 31;
        float inv = powf(10000.0f, -(2.0f * (float)i) / 64.0f);
        float s = 0.0f;
        for (int t = 0; t < 16; ++t) {
            float a = (float)(bin * 16 + t) * inv;
            s += (j < 32) ? sinf(a) : cosf(a);
        }
        d_tabR[e] = s;
    } else if (idx < 16896 + 16384) {
        int e = idx - 16896;
        d_pwT[e] = pw[(e & 127) * 128 + (e >> 7)];
    } else if (idx < 16896 + 16384 + 32768) {
        int e = idx - (16896 + 16384);
        d_WkvT[e] = Wkv[(e & 255) * 128 + (e >> 8)];
    } else if (idx < 66048 + 32768) {
        int i = idx - 66048;
        const float* W; unsigned char *H, *L; int e;
        if (i < 16384) { W = Wq; H = d_wqh; L = d_wql; e = i; }
        else           { W = Wp; H = d_wph; L = d_wpl; e = i - 16384; }
        int o = e >> 7, c = e & 127;
        float v = W[e];
        __nv_bfloat16 h = __float2bfloat16(v);
        float r = v - __bfloat162float(h);
        uint32_t off = (uint32_t)(o * TSTR + c * 2);
        *(__nv_bfloat16*)(H + off) = h;
        *(__nv_bfloat16*)(L + off) = __float2bfloat16(r);
    }
}

// ---------------- K1: ASPP pooling + depthwise conv (validated) -------------
__global__ void k_pool_dw(const float* __restrict__ x, const float* __restrict__ dw) {
    __shared__ float pm[64];
    __shared__ float g4[16];
    __shared__ float g2[4];
    __shared__ float g1[1];
    int tid = threadIdx.x;
    int b = blockIdx.x >> 7, c = blockIdx.x & 127;
    if (tid < 64) pm[tid] = 0.0f;
    __syncthreads();
    int r = tid >> 1, hf = tid & 1;
    const float4* xr = (const float4*)(x + ((size_t)(b * NC + c) << 14) + (r << 7) + (hf << 6));
    float sbin[4] = {0.0f, 0.0f, 0.0f, 0.0f};
#pragma unroll
    for (int q = 0; q < 16; ++q) {
        float4 v = xr[q];
        sbin[q >> 2] += (v.x + v.y) + (v.z + v.w);
    }
    int by = r >> 4;
#pragma unroll
    for (int t = 0; t < 4; ++t) atomicAdd(&pm[by * 8 + hf * 4 + t], sbin[t]);
    __syncthreads();
    if (tid < 64) {
        int byy = tid >> 3, bx = tid & 7;
        float pe = (c < 64) ? d_tabR[byy * 64 + c] : d_tabR[bx * 64 + (c - 64)];
        pm[tid] = (pm[tid] + 16.0f * pe) * (1.0f / 256.0f);
    }
    __syncthreads();
    if (tid < 16) {
        int i = tid >> 2, j = tid & 3;
        g4[tid] = 0.25f * (pm[(2 * i) * 8 + 2 * j] + pm[(2 * i) * 8 + 2 * j + 1] +
                           pm[(2 * i + 1) * 8 + 2 * j] + pm[(2 * i + 1) * 8 + 2 * j + 1]);
    } else if (tid < 20) {
        int t = tid - 16, i = t >> 1, j = t & 1;
        float s = 0.0f;
        for (int yy = 0; yy < 4; ++yy)
            for (int xq = 0; xq < 4; ++xq) s += pm[(4 * i + yy) * 8 + 4 * j + xq];
        g2[t] = s * (1.0f / 16.0f);
    } else if (tid == 20) {
        float s = 0.0f;
        for (int q = 0; q < 64; ++q) s += pm[q];
        g1[0] = s * (1.0f / 64.0f);
    }
    __syncthreads();
    if (tid < KVL) {
        float wv[9];
#pragma unroll
        for (int q = 0; q < 9; ++q) wv[q] = dw[c * 9 + q];
        const float* g; int s, ly, lx;
        if (tid < 64)      { g = pm; s = 8; ly = tid >> 3;        lx = tid & 7; }
        else if (tid < 80) { int t = tid - 64; g = g4; s = 4; ly = t >> 2; lx = t & 3; }
        else if (tid < 84) { int t = tid - 80; g = g2; s = 2; ly = t >> 1; lx = t & 1; }
        else               { g = g1; s = 1; ly = 0; lx = 0; }
        float a = 0.0f;
#pragma unroll
        for (int ky = 0; ky < 3; ++ky) {
            int iy = ly + ky - 1;
            bool oky = (iy >= 0) && (iy < s);
#pragma unroll
            for (int kx = 0; kx < 3; ++kx) {
                int ix = lx + kx - 1;
                if (oky && ix >= 0 && ix < s) a += g[iy * s + ix] * wv[ky * 3 + kx];
            }
        }
        d_y1[((size_t)b * KVL + tid) * NC + c] = a;
    }
}

// ---------------- K2: pointwise -> LN -> GELU -> KV proj (validated) --------
__global__ void k_pw_ln_kv(const float* __restrict__ lnw, const float* __restrict__ lnb) {
    __shared__ float ycol[128];
    __shared__ float part[256];
    __shared__ float zs[128];
    __shared__ float red[2];
    int tid = threadIdx.x;
    int b = blockIdx.x / KVL;
    int row = blockIdx.x - b * KVL;
    if (tid < 128) ycol[tid] = d_y1[((size_t)b * KVL + row) * NC + tid];
    __syncthreads();
    {
        int o = tid & 127, half = tid >> 7;
        const float* wc = d_pwT + (half << 6) * 128 + o;
        const float* yc = ycol + (half << 6);
        float a = 0.0f;
#pragma unroll 8
        for (int ci = 0; ci < 64; ++ci) a += wc[ci * 128] * yc[ci];
        part[tid] = a;
    }
    __syncthreads();
    if (tid < 128) zs[tid] = part[tid] + part[tid + 128];
    __syncthreads();
    if (tid < 32) {
        float s = zs[tid] + zs[tid + 32] + zs[tid + 64] + zs[tid + 96];
#pragma unroll
        for (int o = 16; o; o >>= 1) s += __shfl_xor_sync(0xffffffffu, s, o);
        if (tid == 0) red[0] = s * (1.0f / 128.0f);
    }
    __syncthreads();
    float mu = red[0];
    if (tid < 32) {
        float s = 0.0f;
#pragma unroll
        for (int q = 0; q < 4; ++q) { float dd = zs[tid + 32 * q] - mu; s += dd * dd; }
#pragma unroll
        for (int o = 16; o; o >>= 1) s += __shfl_xor_sync(0xffffffffu, s, o);
        if (tid == 0) red[1] = s * (1.0f / 128.0f);
    }
    __syncthreads();
    float rstd = rsqrtf(red[1] + 1e-5f);
    if (tid < 128) {
        float zn = (zs[tid] - mu) * rstd * lnw[tid] + lnb[tid];
        zs[tid] = 0.5f * zn * (1.0f + erff(zn * 0.70710678118654752f));
    }
    __syncthreads();
    float a = 0.0f;
    const float* wc = d_WkvT + tid;
#pragma unroll 8
    for (int ci = 0; ci < 128; ++ci) a += wc[ci * 256] * zs[ci];
    int m = (tid >> 4) & 7, d = tid & 15;
    float* dst = (tid < 128) ? d_k : d_v;
    dst[((size_t)(b * NH + m) * KVL + row) * HD + d] = a;
}

// ---------------- K3: fused main (HMMA projections, 1024 threads) -----------
#define OWH 0
#define OWL TILEB
#define OXH (2 * TILEB)
#define OXL (3 * TILEB)
#define OKS (4 * TILEB)
#define OVS (OKS + 43520)
#define OBI (OVS + 43520)
#define SMB (OBI + 512 + 16)

#define LDMX4(r0, r1, r2, r3, a) \
    asm volatile("ldmatrix.sync.aligned.m8n8.x4.shared.b16 {%0,%1,%2,%3}, [%4];" \
        : "=r"(r0), "=r"(r1), "=r"(r2), "=r"(r3) : "r"(a))
#define LDMX2(r0, r1, a) \
    asm volatile("ldmatrix.sync.aligned.m8n8.x2.shared.b16 {%0,%1}, [%2];" \
        : "=r"(r0), "=r"(r1) : "r"(a))
#define MMA16816(d, a0, a1, a2, a3, b0, b1) \
    asm volatile("mma.sync.aligned.m16n8k16.row.col.f32.bf16.bf16.f32 " \
        "{%0,%1,%2,%3}, {%4,%5,%6,%7}, {%8,%9}, {%0,%1,%2,%3};" \
        : "+f"((d)[0]), "+f"((d)[1]), "+f"((d)[2]), "+f"((d)[3]) \
        : "r"(a0), "r"(a1), "r"(a2), "r"(a3), "r"(b0), "r"(b1))

// D[c][p] = sum_k W[c][k] * X[p][k], bf16 hi/lo 3-chain split.
// 32 warps: m-tile = w&7 (16 channels), n-quarter = w>>3 (32 pixels = 4 n8-tiles)
__device__ __forceinline__ void hmma_gemm(uint32_t sb, uint32_t aBase, uint32_t bBase,
                                          int w, int lane, float D[4][4]) {
#pragma unroll
    for (int n = 0; n < 4; ++n)
#pragma unroll
        for (int q = 0; q < 4; ++q) D[n][q] = 0.0f;
    int mt = w & 7, nq = w >> 3;
    int sub = lane >> 3, r = lane & 7;
    uint32_t aH = sb + aBase + (uint32_t)((mt * 16 + (sub & 1) * 8 + r) * TSTR + (sub >> 1) * 16);
    uint32_t aL = aH + TILEB;
    int bl = lane & 15;
    uint32_t bH = sb + bBase + (uint32_t)((nq * 32 + (bl & 7)) * TSTR + (bl >> 3) * 16);
    uint32_t bL = bH + TILEB;
#pragma unroll
    for (int kc = 0; kc < 8; ++kc) {
        uint32_t ah0, ah1, ah2, ah3, al0, al1, al2, al3;
        LDMX4(ah0, ah1, ah2, ah3, aH + kc * 32);
        LDMX4(al0, al1, al2, al3, aL + kc * 32);
#pragma unroll
        for (int n = 0; n < 4; ++n) {
            uint32_t bh0, bh1, bl0, bl1;
            LDMX2(bh0, bh1, bH + n * (8 * TSTR) + kc * 32);
            LDMX2(bl0, bl1, bL + n * (8 * TSTR) + kc * 32);
            MMA16816(D[n], ah0, ah1, ah2, ah3, bh0, bh1);
            MMA16816(D[n], al0, al1, al2, al3, bh0, bh1);
            MMA16816(D[n], ah0, ah1, ah2, ah3, bl0, bl1);
        }
    }
}

__global__ void __launch_bounds__(1024, 1)
k_main(const float* __restrict__ x, const float* __restrict__ bproj,
       float* __restrict__ out) {
    extern __shared__ char smc[];
    uint32_t sb;
    asm("{ .reg .u64 t; cvta.to.shared.u64 t, %1; cvt.u32.u64 %0, t; }" : "=r"(sb) : "l"(smc));
    int tid = threadIdx.x, w = tid >> 5, lane = tid & 31;
    int b = blockIdx.x >> 7, y = blockIdx.x & 127;

    if (tid < 128) ((float*)(smc + OBI))[tid] = bproj[tid];
    {   // K/V
        const float4* kg = (const float4*)(d_k + (size_t)b * NH * KVS);
        const float4* vg = (const float4*)(d_v + (size_t)b * NH * KVS);
        float4* ks = (float4*)(smc + OKS);
        float4* vs = (float4*)(smc + OVS);
        for (int i = tid; i < NH * KVS / 4; i += 1024) { ks[i] = kg[i]; vs[i] = vg[i]; }
    }
    {   // Wq bf16 tiles
        const float4* h4 = (const float4*)d_wqh;
        const float4* l4 = (const float4*)d_wql;
        float4* wh = (float4*)(smc + OWH);
        float4* wl = (float4*)(smc + OWL);
        for (int i = tid; i < TILEB / 16; i += 1024) { wh[i] = h4[i]; wl[i] = l4[i]; }
    }
    {   // Xp bf16 split tiles: rows = pixels p, cols = channels c
        int p = tid & 127;
        int yoff = y << 7;
        for (int g = tid >> 7; g < 64; g += 8) {
            int c0 = g * 2, c1 = c0 + 1;
            float v0 = x[((size_t)(b * NC + c0) << 14) + yoff + p];
            float v1 = x[((size_t)(b * NC + c1) << 14) + yoff + p];
            v0 += (c0 < 64) ? d_tab[y * 64 + c0] : d_tabT[(c0 - 64) * 128 + p];
            v1 += (c1 < 64) ? d_tab[y * 64 + c1] : d_tabT[(c1 - 64) * 128 + p];
            __nv_bfloat162 hh = __floats2bfloat162_rn(v0, v1);
            __nv_bfloat162 ll = __floats2bfloat162_rn(v0 - __bfloat162float(hh.x),
                                                      v1 - __bfloat162float(hh.y));
            uint32_t off = (uint32_t)(p * TSTR + c0 * 2);
            *(uint32_t*)(smc + OXH + off) = bf2u(hh);
            *(uint32_t*)(smc + OXL + off) = bf2u(ll);
        }
    }
    __syncthreads();

    float D[4][4];
    // ---- Q-GEMM (HMMA) ----
    hmma_gemm(sb, OWH, OXH, w, lane, D);
    __syncthreads();   // all Wq/Xp reads done; OWH/OWL become Q fp32 [c][p]

    float* Qs = (float*)(smc + OWH);
    {
        int mt = w & 7, nq = w >> 3;
        int rc = mt * 16 + (lane >> 2);
#pragma unroll
        for (int n = 0; n < 4; ++n) {
            int p0 = nq * 32 + n * 8 + (lane & 3) * 2;
            *(float2*)&Qs[rc * 128 + p0] = make_float2(D[n][0] * 0.25f, D[n][1] * 0.25f);
            *(float2*)&Qs[(rc + 8) * 128 + p0] = make_float2(D[n][2] * 0.25f, D[n][3] * 0.25f);
        }
    }
    __syncthreads();

    // ---- load Q to regs: thread = (head th, pixel xx) ----
    int th = tid >> 7, xx = tid & 127;
    u64 q0[8];
#pragma unroll
    for (int op = 0; op < 8; ++op) {
        int c = th * 16 + 2 * op;
        q0[op] = pack2(Qs[c * 128 + xx], Qs[(c + 1) * 128 + xx]);
    }
    __syncthreads();   // Q consumed; OWH/OWL free for Wproj

    {   // Wproj bf16 tiles
        const float4* h4 = (const float4*)d_wph;
        const float4* l4 = (const float4*)d_wpl;
        float4* wh = (float4*)(smc + OWH);
        float4* wl = (float4*)(smc + OWL);
        for (int i = tid; i < TILEB / 16; i += 1024) { wh[i] = h4[i]; wl[i] = l4[i]; }
    }

    // ---- attention: 1 pixel per thread (K/V loads warp-broadcast) ----
    const u64* kb = (const u64*)((const float*)(smc + OKS) + th * KVS);
    const u64* vb = (const u64*)((const float*)(smc + OVS) + th * KVS);
    u64 oa0[8];
#pragma unroll
    for (int i = 0; i < 8; ++i) oa0[i] = 0ull;
    float s0 = 0.0f;
#pragma unroll 4
    for (int j = 0; j < KVL; ++j) {
        const float* kf = (const float*)(kb + j * 8);
        ulonglong2 k01 = *(const ulonglong2*)(kf);
        ulonglong2 k23 = *(const ulonglong2*)(kf + 4);
        ulonglong2 k45 = *(const ulonglong2*)(kf + 8);
        ulonglong2 k67 = *(const ulonglong2*)(kf + 12);
        u64 d00 = mul2(q0[0], k01.x), d01 = mul2(q0[1], k01.y);
        d00 = fma2(q0[2], k23.x, d00);  d01 = fma2(q0[3], k23.y, d01);
        d00 = fma2(q0[4], k45.x, d00);  d01 = fma2(q0[5], k45.y, d01);
        d00 = fma2(q0[6], k67.x, d00);  d01 = fma2(q0[7], k67.y, d01);
        float a0, b0, c0f, e0l;
        unpack2(d00, a0, b0); unpack2(d01, c0f, e0l);
        float e0 = __expf((a0 + b0) + (c0f + e0l));
        s0 += e0;
        u64 p0 = splat2(e0);
        const float* vf = (const float*)(vb + j * 8);
        ulonglong2 v01 = *(const ulonglong2*)(vf);
        ulonglong2 v23 = *(const ulonglong2*)(vf + 4);
        ulonglong2 v45 = *(const ulonglong2*)(vf + 8);
        ulonglong2 v67 = *(const ulonglong2*)(vf + 12);
        oa0[0] = fma2(p0, v01.x, oa0[0]);
        oa0[1] = fma2(p0, v01.y, oa0[1]);
        oa0[2] = fma2(p0, v23.x, oa0[2]);
        oa0[3] = fma2(p0, v23.y, oa0[3]);
        oa0[4] = fma2(p0, v45.x, oa0[4]);
        oa0[5] = fma2(p0, v45.y, oa0[5]);
        oa0[6] = fma2(p0, v67.x, oa0[6]);
        oa0[7] = fma2(p0, v67.y, oa0[7]);
    }
    {   // O bf16-split into X tiles (rows = pixels, cols = channels)
        float i0 = 1.0f / s0;
#pragma unroll
        for (int i = 0; i < 8; ++i) {
            int c0 = th * 16 + 2 * i;
            float lo, hi;
            unpack2(oa0[i], lo, hi);
            float g0 = lo * i0, g1 = hi * i0;
            __nv_bfloat162 hh = __floats2bfloat162_rn(g0, g1);
            __nv_bfloat162 ll = __floats2bfloat162_rn(g0 - __bfloat162float(hh.x),
                                                      g1 - __bfloat162float(hh.y));
            uint32_t off = (uint32_t)(xx * TSTR + c0 * 2);
            *(uint32_t*)(smc + OXH + off) = bf2u(hh);
            *(uint32_t*)(smc + OXL + off) = bf2u(ll);
        }
    }
    __syncthreads();   // O tiles + Wproj ready

    // ---- out-proj GEMM (HMMA) + bias + store ----
    hmma_gemm(sb, OWH, OXH, w, lane, D);
    {
        const float* bias = (const float*)(smc + OBI);
        int mt = w & 7, nq = w >> 3;
        int rc = mt * 16 + (lane >> 2);
        float b0 = bias[rc], b1 = bias[rc + 8];
        float* og = out + (((size_t)b * NC) << 14) + (y << 7);
#pragma unroll
        for (int n = 0; n < 4; ++n) {
            int p0 = nq * 32 + n * 8 + (lane & 3) * 2;
            *(float2*)(og + (((size_t)rc) << 14) + p0) =
                make_float2(D[n][0] + b0, D[n][1] + b0);
            *(float2*)(og + (((size_t)(rc + 8)) << 14) + p0) =
                make_float2(D[n][2] + b1, D[n][3] + b1);
        }
    }
}

// ----------------------------------------------------------------------------
extern "C" void kernel_launch(void* const* d_in, const int* in_sizes, int n_in,
                              void* d_out, int out_size) {
    const float* x     = (const float*)d_in[0];
    const float* Wq    = (const float*)d_in[1];
    const float* Wkv   = (const float*)d_in[2];
    const float* Wproj = (const float*)d_in[3];
    const float* bproj = (const float*)d_in[4];
    const float* dw    = (const float*)d_in[5];
    const float* pw    = (const float*)d_in[6];
    const float* lnw   = (const float*)d_in[7];
    const float* lnb   = (const float*)d_in[8];
    float* out = (float*)d_out;

    cudaFuncSetAttribute(k_main, cudaFuncAttributeMaxDynamicSharedMemorySize, SMB);

    k_prep<<<386, 256>>>(pw, Wkv, Wq, Wproj);
    k_pool_dw<<<NB * NC, 256>>>(x, dw);
    k_pw_ln_kv<<<NB * KVL, 256>>>(lnw, lnb);
    k_main<<<NB * 128, 1024, SMB>>>(x, bproj, out);
}

// round 12
// speedup vs baseline: 1.6843x; 1.2438x over previous
#include <cuda_runtime.h>
#include <cuda_bf16.h>
#include <math.h>
#include <stdint.h>

#define NB 8
#define NC 128
#define NH 8
#define HD 16
#define KVL 85

#define TSTR 272
#define TILEB (128 * TSTR)   // 34816
#define KSTRIDE 144
#define KTILE (96 * KSTRIDE) // 13824 bytes: rows=kv(96), cols=4 heads x 16c
#define VSTRIDE 208
#define VTILE (64 * VSTRIDE) // 13312 bytes: rows=4 heads x 16c, cols=j(96 pad 104)

__device__ __align__(16) float d_tab[128 * 64];
__device__ __align__(16) float d_tabT[64 * 128];
__device__ __align__(16) float d_tabR[8 * 64];
__device__ __align__(16) float d_y1[NB * KVL * NC];
__device__ __align__(16) float d_pwT[128 * 128];
__device__ __align__(16) float d_WkvT[128 * 256];
__device__ __align__(16) unsigned char d_wqh[TILEB];
__device__ __align__(16) unsigned char d_wql[TILEB];
__device__ __align__(16) unsigned char d_wph[TILEB];
__device__ __align__(16) unsigned char d_wpl[TILEB];
__device__ __align__(16) unsigned char d_kth[NB * 2 * KTILE];
__device__ __align__(16) unsigned char d_ktl[NB * 2 * KTILE];
__device__ __align__(16) unsigned char d_vth[NB * 2 * VTILE];
__device__ __align__(16) unsigned char d_vtl[NB * 2 * VTILE];

__device__ __forceinline__ uint32_t bf2u(__nv_bfloat162 v) {
    return ((uint32_t)__bfloat16_as_ushort(v.y) << 16) | (uint32_t)__bfloat16_as_ushort(v.x);
}
// pack two fp32 -> bf16x2 hi/lo pair (lo half = first element)
__device__ __forceinline__ void bfsplit(float v0, float v1, uint32_t& hi, uint32_t& lo) {
    __nv_bfloat162 hh = __floats2bfloat162_rn(v0, v1);
    __nv_bfloat162 ll = __floats2bfloat162_rn(v0 - __bfloat162float(hh.x),
                                              v1 - __bfloat162float(hh.y));
    hi = bf2u(hh); lo = bf2u(ll);
}

// ---------------- K0: tables + transposes + weight split + KV zero ----------
__global__ void k_prep(const float* __restrict__ pw, const float* __restrict__ Wkv,
                       const float* __restrict__ Wq, const float* __restrict__ Wp) {
    int idx = blockIdx.x * 256 + threadIdx.x;
    if (idx < 8192) {
        int yv = idx >> 6, j = idx & 63, i = j & 31;
        float inv = powf(10000.0f, -(2.0f * (float)i) / 64.0f);
        float a = (float)yv * inv;
        d_tab[idx] = (j < 32) ? sinf(a) : cosf(a);
    } else if (idx < 16384) {
        int e = idx - 8192;
        int j = e >> 7, p = e & 127, i = j & 31;
        float inv = powf(10000.0f, -(2.0f * (float)i) / 64.0f);
        float a = (float)p * inv;
        d_tabT[e] = (j < 32) ? sinf(a) : cosf(a);
    } else if (idx < 16896) {
        int e = idx - 16384;
        int bin = e >> 6, j = e & 63, i = j & 31;
        float inv = powf(10000.0f, -(2.0f * (float)i) / 64.0f);
        float s = 0.0f;
        for (int t = 0; t < 16; ++t) {
            float a = (float)(bin * 16 + t) * inv;
            s += (j < 32) ? sinf(a) : cosf(a);
        }
        d_tabR[e] = s;
    } else if (idx < 33280) {
        int e = idx - 16896;
        d_pwT[e] = pw[(e & 127) * 128 + (e >> 7)];
    } else if (idx < 66048) {
        int e = idx - 33280;
        d_WkvT[e] = Wkv[(e & 255) * 128 + (e >> 8)];
    } else if (idx < 98816) {
        int i = idx - 66048;
        const float* W; unsigned char *H, *L; int e;
        if (i < 16384) { W = Wq; H = d_wqh; L = d_wql; e = i; }
        else           { W = Wp; H = d_wph; L = d_wpl; e = i - 16384; }
        int o = e >> 7, c = e & 127;
        float v = W[e];
        __nv_bfloat16 h = __float2bfloat16(v);
        float r = v - __bfloat162float(h);
        uint32_t off = (uint32_t)(o * TSTR + c * 2);
        *(__nv_bfloat16*)(H + off) = h;
        *(__nv_bfloat16*)(L + off) = __float2bfloat16(r);
    } else if (idx < 98816 + 55296) {
        ((uint32_t*)d_kth)[idx - 98816] = 0;
    } else if (idx < 98816 + 110592) {
        ((uint32_t*)d_ktl)[idx - 98816 - 55296] = 0;
    } else if (idx < 98816 + 110592 + 53248) {
        ((uint32_t*)d_vth)[idx - 98816 - 110592] = 0;
    } else if (idx < 98816 + 110592 + 106496) {
        ((uint32_t*)d_vtl)[idx - 98816 - 110592 - 53248] = 0;
    }
}

// ---------------- K1: ASPP pooling + depthwise conv (validated) -------------
__global__ void k_pool_dw(const float* __restrict__ x, const float* __restrict__ dw) {
    __shared__ float pm[64];
    __shared__ float g4[16];
    __shared__ float g2[4];
    __shared__ float g1[1];
    int tid = threadIdx.x;
    int b = blockIdx.x >> 7, c = blockIdx.x & 127;
    if (tid < 64) pm[tid] = 0.0f;
    __syncthreads();
    int r = tid >> 1, hf = tid & 1;
    const float4* xr = (const float4*)(x + ((size_t)(b * NC + c) << 14) + (r << 7) + (hf << 6));
    float sbin[4] = {0.0f, 0.0f, 0.0f, 0.0f};
#pragma unroll
    for (int q = 0; q < 16; ++q) {
        float4 v = xr[q];
        sbin[q >> 2] += (v.x + v.y) + (v.z + v.w);
    }
    int by = r >> 4;
#pragma unroll
    for (int t = 0; t < 4; ++t) atomicAdd(&pm[by * 8 + hf * 4 + t], sbin[t]);
    __syncthreads();
    if (tid < 64) {
        int byy = tid >> 3, bx = tid & 7;
        float pe = (c < 64) ? d_tabR[byy * 64 + c] : d_tabR[bx * 64 + (c - 64)];
        pm[tid] = (pm[tid] + 16.0f * pe) * (1.0f / 256.0f);
    }
    __syncthreads();
    if (tid < 16) {
        int i = tid >> 2, j = tid & 3;
        g4[tid] = 0.25f * (pm[(2 * i) * 8 + 2 * j] + pm[(2 * i) * 8 + 2 * j + 1] +
                           pm[(2 * i + 1) * 8 + 2 * j] + pm[(2 * i + 1) * 8 + 2 * j + 1]);
    } else if (tid < 20) {
        int t = tid - 16, i = t >> 1, j = t & 1;
        float s = 0.0f;
        for (int yy = 0; yy < 4; ++yy)
            for (int xq = 0; xq < 4; ++xq) s += pm[(4 * i + yy) * 8 + 4 * j + xq];
        g2[t] = s * (1.0f / 16.0f);
    } else if (tid == 20) {
        float s = 0.0f;
        for (int q = 0; q < 64; ++q) s += pm[q];
        g1[0] = s * (1.0f / 64.0f);
    }
    __syncthreads();
    if (tid < KVL) {
        float wv[9];
#pragma unroll
        for (int q = 0; q < 9; ++q) wv[q] = dw[c * 9 + q];
        const float* g; int s, ly, lx;
        if (tid < 64)      { g = pm; s = 8; ly = tid >> 3;        lx = tid & 7; }
        else if (tid < 80) { int t = tid - 64; g = g4; s = 4; ly = t >> 2; lx = t & 3; }
        else if (tid < 84) { int t = tid - 80; g = g2; s = 2; ly = t >> 1; lx = t & 1; }
        else               { g = g1; s = 1; ly = 0; lx = 0; }
        float a = 0.0f;
#pragma unroll
        for (int ky = 0; ky < 3; ++ky) {
            int iy = ly + ky - 1;
            bool oky = (iy >= 0) && (iy < s);
#pragma unroll
            for (int kx = 0; kx < 3; ++kx) {
                int ix = lx + kx - 1;
                if (oky && ix >= 0 && ix < s) a += g[iy * s + ix] * wv[ky * 3 + kx];
            }
        }
        d_y1[((size_t)b * KVL + tid) * NC + c] = a;
    }
}

// ---------------- K2: pointwise -> LN -> GELU -> KV proj (bf16 tiles) -------
__global__ void k_pw_ln_kv(const float* __restrict__ lnw, const float* __restrict__ lnb) {
    __shared__ float ycol[128];
    __shared__ float part[256];
    __shared__ float zs[128];
    __shared__ float red[2];
    int tid = threadIdx.x;
    int b = blockIdx.x / KVL;
    int row = blockIdx.x - b * KVL;
    if (tid < 128) ycol[tid] = d_y1[((size_t)b * KVL + row) * NC + tid];
    __syncthreads();
    {
        int o = tid & 127, half = tid >> 7;
        const float* wc = d_pwT + (half << 6) * 128 + o;
        const float* yc = ycol + (half << 6);
        float a = 0.0f;
#pragma unroll 8
        for (int ci = 0; ci < 64; ++ci) a += wc[ci * 128] * yc[ci];
        part[tid] = a;
    }
    __syncthreads();
    if (tid < 128) zs[tid] = part[tid] + part[tid + 128];
    __syncthreads();
    if (tid < 32) {
        float s = zs[tid] + zs[tid + 32] + zs[tid + 64] + zs[tid + 96];
#pragma unroll
        for (int o = 16; o; o >>= 1) s += __shfl_xor_sync(0xffffffffu, s, o);
        if (tid == 0) red[0] = s * (1.0f / 128.0f);
    }
    __syncthreads();
    float mu = red[0];
    if (tid < 32) {
        float s = 0.0f;
#pragma unroll
        for (int q = 0; q < 4; ++q) { float dd = zs[tid + 32 * q] - mu; s += dd * dd; }
#pragma unroll
        for (int o = 16; o; o >>= 1) s += __shfl_xor_sync(0xffffffffu, s, o);
        if (tid == 0) red[1] = s * (1.0f / 128.0f);
    }
    __syncthreads();
    float rstd = rsqrtf(red[1] + 1e-5f);
    if (tid < 128) {
        float zn = (zs[tid] - mu) * rstd * lnw[tid] + lnb[tid];
        zs[tid] = 0.5f * zn * (1.0f + erff(zn * 0.70710678118654752f));
    }
    __syncthreads();
    float a = 0.0f;
    const float* wc = d_WkvT + tid;
#pragma unroll 8
    for (int ci = 0; ci < 128; ++ci) a += wc[ci * 256] * zs[ci];
    __nv_bfloat16 h = __float2bfloat16(a);
    __nv_bfloat16 l = __float2bfloat16(a - __bfloat162float(h));
    if (tid < 128) {       // K: tile rows=kv, cols=(head&3)*16+d, stage=head>>2
        int m = tid >> 4, d = tid & 15, s = m >> 2;
        uint32_t off = ((uint32_t)(b * 2 + s) * 96 + row) * KSTRIDE + (m & 3) * 32 + d * 2;
        *(__nv_bfloat16*)(d_kth + off) = h;
        *(__nv_bfloat16*)(d_ktl + off) = l;
    } else {               // V^T: tile rows=(head&3)*16+d, cols=j
        int cc = tid - 128;
        int m = cc >> 4, d = cc & 15, s = m >> 2;
        uint32_t off = ((uint32_t)(b * 2 + s) * 64 + (m & 3) * 16 + d) * VSTRIDE + row * 2;
        *(__nv_bfloat16*)(d_vth + off) = h;
        *(__nv_bfloat16*)(d_vtl + off) = l;
    }
}

// ---------------- K3: fused main — HMMA everywhere ----------------
#define OXH 0
#define OXL TILEB
#define OWH (2 * TILEB)
#define OWL (3 * TILEB)
#define OKH (4 * TILEB)          // 139264
#define OKL (OKH + KTILE)
#define OVH (OKL + KTILE)        // 166912
#define OVL (OVH + VTILE)
#define OBI (OVL + VTILE)        // 193536
#define SMB (OBI + 512 + 64)

#define LDMX4(r0, r1, r2, r3, a) \
    asm volatile("ldmatrix.sync.aligned.m8n8.x4.shared.b16 {%0,%1,%2,%3}, [%4];" \
        : "=r"(r0), "=r"(r1), "=r"(r2), "=r"(r3) : "r"(a))
#define LDMX2(r0, r1, a) \
    asm volatile("ldmatrix.sync.aligned.m8n8.x2.shared.b16 {%0,%1}, [%2];" \
        : "=r"(r0), "=r"(r1) : "r"(a))
#define MMA16816(d, a0, a1, a2, a3, b0, b1) \
    asm volatile("mma.sync.aligned.m16n8k16.row.col.f32.bf16.bf16.f32 " \
        "{%0,%1,%2,%3}, {%4,%5,%6,%7}, {%8,%9}, {%0,%1,%2,%3};" \
        : "+f"((d)[0]), "+f"((d)[1]), "+f"((d)[2]), "+f"((d)[3]) \
        : "r"(a0), "r"(a1), "r"(a2), "r"(a3), "r"(b0), "r"(b1))

// D[m=A-rows][n=B-rows]: 16 warps, mt=w&7 (16 A-rows), nw=w>>3 (2 x 64 B-rows)
__device__ __forceinline__ void hmma_gemm(uint32_t sb, uint32_t aBase, uint32_t bBase,
                                          int w, int lane, float D[8][4]) {
#pragma unroll
    for (int n = 0; n < 8; ++n)
#pragma unroll
        for (int q = 0; q < 4; ++q) D[n][q] = 0.0f;
    int mt = w & 7, nw = w >> 3;
    int sub = lane >> 3, r = lane & 7;
    uint32_t aH = sb + aBase + (uint32_t)((mt * 16 + (sub & 1) * 8 + r) * TSTR + (sub >> 1) * 16);
    uint32_t aL = aH + TILEB;
    int bl = lane & 15;
    uint32_t bH = sb + bBase + (uint32_t)((nw * 64 + (bl & 7)) * TSTR + (bl >> 3) * 16);
    uint32_t bL = bH + TILEB;
#pragma unroll
    for (int kc = 0; kc < 8; ++kc) {
        uint32_t ah0, ah1, ah2, ah3, al0, al1, al2, al3;
        LDMX4(ah0, ah1, ah2, ah3, aH + kc * 32);
        LDMX4(al0, al1, al2, al3, aL + kc * 32);
#pragma unroll
        for (int n = 0; n < 8; ++n) {
            uint32_t bh0, bh1, bl0, bl1;
            LDMX2(bh0, bh1, bH + n * (8 * TSTR) + kc * 32);
            LDMX2(bl0, bl1, bL + n * (8 * TSTR) + kc * 32);
            MMA16816(D[n], ah0, ah1, ah2, ah3, bh0, bh1);
            MMA16816(D[n], al0, al1, al2, al3, bh0, bh1);
            MMA16816(D[n], ah0, ah1, ah2, ah3, bl0, bl1);
        }
    }
}

__device__ __forceinline__ void fill_kv(char* smc, int tid, int b, int s) {
    const float4* kh = (const float4*)(d_kth + (size_t)(b * 2 + s) * KTILE);
    const float4* kl = (const float4*)(d_ktl + (size_t)(b * 2 + s) * KTILE);
    const float4* vh = (const float4*)(d_vth + (size_t)(b * 2 + s) * VTILE);
    const float4* vl = (const float4*)(d_vtl + (size_t)(b * 2 + s) * VTILE);
    float4* dkh = (float4*)(smc + OKH);
    float4* dkl = (float4*)(smc + OKL);
    float4* dvh = (float4*)(smc + OVH);
    float4* dvl = (float4*)(smc + OVL);
    for (int i = tid; i < KTILE / 16; i += 512) { dkh[i] = kh[i]; dkl[i] = kl[i]; }
    for (int i = tid; i < VTILE / 16; i += 512) { dvh[i] = vh[i]; dvl[i] = vl[i]; }
}

__global__ void __launch_bounds__(512, 1)
k_main(const float* __restrict__ x, const float* __restrict__ bproj,
       float* __restrict__ out) {
    extern __shared__ char smc[];
    uint32_t sb;
    asm("{ .reg .u64 t; cvta.to.shared.u64 t, %1; cvt.u32.u64 %0, t; }" : "=r"(sb) : "l"(smc));
    int tid = threadIdx.x, w = tid >> 5, lane = tid & 31;
    int b = blockIdx.x >> 7, y = blockIdx.x & 127;

    if (tid < 128) ((float*)(smc + OBI))[tid] = bproj[tid];
    {   // Wq tiles
        const float4* h4 = (const float4*)d_wqh;
        const float4* l4 = (const float4*)d_wql;
        float4* wh = (float4*)(smc + OWH);
        float4* wl = (float4*)(smc + OWL);
        for (int i = tid; i < TILEB / 16; i += 512) { wh[i] = h4[i]; wl[i] = l4[i]; }
    }
    {   // Xp bf16 split tiles: rows=px, cols=c
        int p = tid & 127;
        int yoff = y << 7;
        for (int g = tid >> 7; g < 64; g += 4) {
            int c0 = g * 2, c1 = c0 + 1;
            float v0 = x[((size_t)(b * NC + c0) << 14) + yoff + p];
            float v1 = x[((size_t)(b * NC + c1) << 14) + yoff + p];
            v0 += (c0 < 64) ? d_tab[y * 64 + c0] : d_tabT[(c0 - 64) * 128 + p];
            v1 += (c1 < 64) ? d_tab[y * 64 + c1] : d_tabT[(c1 - 64) * 128 + p];
            uint32_t hi, lo;
            bfsplit(v0, v1, hi, lo);
            uint32_t off = (uint32_t)(p * TSTR + c0 * 2);
            *(uint32_t*)(smc + OXH + off) = hi;
            *(uint32_t*)(smc + OXL + off) = lo;
        }
    }
    fill_kv(smc, tid, b, 0);
    __syncthreads();

    float D[8][4];
    // ---- Q-GEMM: D[px][c] (A = X, B = Wq) ----
    hmma_gemm(sb, OXH, OWH, w, lane, D);
    __syncthreads();   // Wq reads done

    {   // write Q bf16 hi/lo (x0.25) into OWH/OWL, rows=px cols=c
        int mt = w & 7, nw = w >> 3;
        int rr = lane >> 2, q = lane & 3;
        int px0 = mt * 16 + rr;
#pragma unroll
        for (int n = 0; n < 8; ++n) {
            int c = nw * 64 + n * 8 + q * 2;
            uint32_t hi, lo;
            bfsplit(D[n][0] * 0.25f, D[n][1] * 0.25f, hi, lo);
            *(uint32_t*)(smc + OWH + px0 * TSTR + c * 2) = hi;
            *(uint32_t*)(smc + OWL + px0 * TSTR + c * 2) = lo;
            bfsplit(D[n][2] * 0.25f, D[n][3] * 0.25f, hi, lo);
            *(uint32_t*)(smc + OWH + (px0 + 8) * TSTR + c * 2) = hi;
            *(uint32_t*)(smc + OWL + (px0 + 8) * TSTR + c * 2) = lo;
        }
    }
    __syncthreads();

    // ---- attention: 2 stages x 2 tasks/warp; task = (head, 16-px tile) ----
    int sub = lane >> 3, r8 = lane & 7, bl = lane & 15, q = lane & 3, rr = lane >> 2;
    for (int s = 0; s < 2; ++s) {
        if (s) { __syncthreads(); fill_kv(smc, tid, b, 1); __syncthreads(); }
#pragma unroll 1
        for (int t = 0; t < 2; ++t) {
            int tt = w + 16 * t;
            int hl = tt >> 3, mt = tt & 7;
            int h = s * 4 + hl;
            // Q A-frags (rows=px, k = head cols)
            uint32_t qa = sb + OWH + (uint32_t)((mt * 16 + (sub & 1) * 8 + r8) * TSTR
                        + h * 32 + (sub >> 1) * 16);
            uint32_t qh0, qh1, qh2, qh3, ql0, ql1, ql2, ql3;
            LDMX4(qh0, qh1, qh2, qh3, qa);
            LDMX4(ql0, ql1, ql2, ql3, qa + TILEB);
            uint32_t kbase = sb + OKH + (uint32_t)((bl & 7) * KSTRIDE + hl * 32 + (bl >> 3) * 16);
            uint32_t vbase = sb + OVH + (uint32_t)((hl * 16 + (bl & 7)) * VSTRIDE + (bl >> 3) * 16);
            float o0[4] = {0, 0, 0, 0}, o1[4] = {0, 0, 0, 0};
            float sr = 0.0f, sr8 = 0.0f;
#pragma unroll
            for (int ks = 0; ks < 6; ++ks) {
                float P0[4] = {0, 0, 0, 0}, P1[4] = {0, 0, 0, 0};
                uint32_t kh0, kh1, kl0, kl1;
                LDMX2(kh0, kh1, kbase + (2 * ks) * (8 * KSTRIDE));
                LDMX2(kl0, kl1, kbase + (2 * ks) * (8 * KSTRIDE) + (OKL - OKH));
                MMA16816(P0, qh0, qh1, qh2, qh3, kh0, kh1);
                MMA16816(P0, ql0, ql1, ql2, ql3, kh0, kh1);
                MMA16816(P0, qh0, qh1, qh2, qh3, kl0, kl1);
                LDMX2(kh0, kh1, kbase + (2 * ks + 1) * (8 * KSTRIDE));
                LDMX2(kl0, kl1, kbase + (2 * ks + 1) * (8 * KSTRIDE) + (OKL - OKH));
                MMA16816(P1, qh0, qh1, qh2, qh3, kh0, kh1);
                MMA16816(P1, ql0, ql1, ql2, ql3, kh0, kh1);
                MMA16816(P1, qh0, qh1, qh2, qh3, kl0, kl1);
                // exp (unnormalized softmax), pack P frags
                float e00 = __expf(P0[0]), e01 = __expf(P0[1]);
                float e02 = __expf(P0[2]), e03 = __expf(P0[3]);
                float e10 = __expf(P1[0]), e11 = __expf(P1[1]);
                float e12 = __expf(P1[2]), e13 = __expf(P1[3]);
                sr += (e00 + e01) + (e10 + e11);
                sr8 += (e02 + e03) + (e12 + e13);
                uint32_t ah0, ah1, ah2, ah3, al0, al1, al2, al3;
                bfsplit(e00, e01, ah0, al0);
                bfsplit(e02, e03, ah1, al1);
                bfsplit(e10, e11, ah2, al2);
                bfsplit(e12, e13, ah3, al3);
                // PV: O[px][c16] += P * V, 2 n-tiles
                uint32_t vh0, vh1, vl0, vl1;
                LDMX2(vh0, vh1, vbase + ks * 32);
                LDMX2(vl0, vl1, vbase + ks * 32 + (OVL - OVH));
                MMA16816(o0, ah0, ah1, ah2, ah3, vh0, vh1);
                MMA16816(o0, al0, al1, al2, al3, vh0, vh1);
                MMA16816(o0, ah0, ah1, ah2, ah3, vl0, vl1);
                LDMX2(vh0, vh1, vbase + 8 * VSTRIDE + ks * 32);
                LDMX2(vl0, vl1, vbase + 8 * VSTRIDE + ks * 32 + (OVL - OVH));
                MMA16816(o1, ah0, ah1, ah2, ah3, vh0, vh1);
                MMA16816(o1, al0, al1, al2, al3, vh0, vh1);
                MMA16816(o1, ah0, ah1, ah2, ah3, vl0, vl1);
            }
            // row sums across quad; subtract 11 pad contributions (exp(0)=1)
            sr += __shfl_xor_sync(0xffffffffu, sr, 1);
            sr += __shfl_xor_sync(0xffffffffu, sr, 2);
            sr8 += __shfl_xor_sync(0xffffffffu, sr8, 1);
            sr8 += __shfl_xor_sync(0xffffffffu, sr8, 2);
            float ir = 1.0f / (sr - 11.0f), ir8 = 1.0f / (sr8 - 11.0f);
            // write O tiles (rows=px, cols=c) into OXH/OXL
            int px0 = mt * 16 + rr;
            int c0 = h * 16 + q * 2;
            uint32_t hi, lo;
            bfsplit(o0[0] * ir, o0[1] * ir, hi, lo);
            *(uint32_t*)(smc + OXH + px0 * TSTR + c0 * 2) = hi;
            *(uint32_t*)(smc + OXL + px0 * TSTR + c0 * 2) = lo;
            bfsplit(o0[2] * ir8, o0[3] * ir8, hi, lo);
            *(uint32_t*)(smc + OXH + (px0 + 8) * TSTR + c0 * 2) = hi;
            *(uint32_t*)(smc + OXL + (px0 + 8) * TSTR + c0 * 2) = lo;
            bfsplit(o1[0] * ir, o1[1] * ir, hi, lo);
            *(uint32_t*)(smc + OXH + px0 * TSTR + (c0 + 8) * 2) = hi;
            *(uint32_t*)(smc + OXL + px0 * TSTR + (c0 + 8) * 2) = lo;
            bfsplit(o1[2] * ir8, o1[3] * ir8, hi, lo);
            *(uint32_t*)(smc + OXH + (px0 + 8) * TSTR + (c0 + 8) * 2) = hi;
            *(uint32_t*)(smc + OXL + (px0 + 8) * TSTR + (c0 + 8) * 2) = lo;
        }
    }
    __syncthreads();
    {   // Wproj tiles (Q dead)
        const float4* h4 = (const float4*)d_wph;
        const float4* l4 = (const float4*)d_wpl;
        float4* wh = (float4*)(smc + OWH);
        float4* wl = (float4*)(smc + OWL);
        for (int i = tid; i < TILEB / 16; i += 512) { wh[i] = h4[i]; wl[i] = l4[i]; }
    }
    __syncthreads();

    // ---- out-proj GEMM: D[px][c] (A = O, B = Wproj) + bias + store ----
    hmma_gemm(sb, OXH, OWH, w, lane, D);
    {
        const float* bias = (const float*)(smc + OBI);
        int mt = w & 7, nw = w >> 3;
        int px0 = mt * 16 + rr;
        float* og = out + (((size_t)b * NC) << 14) + (y << 7);
#pragma unroll
        for (int n = 0; n < 8; ++n) {
            int c0 = nw * 64 + n * 8 + q * 2;
            float b0 = bias[c0], b1 = bias[c0 + 1];
            float* p0 = og + (((size_t)c0) << 14);
            float* p1 = og + (((size_t)(c0 + 1)) << 14);
            p0[px0] = D[n][0] + b0;
            p1[px0] = D[n][1] + b1;
            p0[px0 + 8] = D[n][2] + b0;
            p1[px0 + 8] = D[n][3] + b1;
        }
    }
}

// ----------------------------------------------------------------------------
extern "C" void kernel_launch(void* const* d_in, const int* in_sizes, int n_in,
                              void* d_out, int out_size) {
    const float* x     = (const float*)d_in[0];
    const float* Wq    = (const float*)d_in[1];
    const float* Wkv   = (const float*)d_in[2];
    const float* Wproj = (const float*)d_in[3];
    const float* bproj = (const float*)d_in[4];
    const float* dw    = (const float*)d_in[5];
    const float* pw    = (const float*)d_in[6];
    const float* lnw   = (const float*)d_in[7];
    const float* lnb   = (const float*)d_in[8];
    float* out = (float*)d_out;

    cudaFuncSetAttribute(k_main, cudaFuncAttributeMaxDynamicSharedMemorySize, SMB);

    k_prep<<<1234, 256>>>(pw, Wkv, Wq, Wproj);
    k_pool_dw<<<NB * NC, 256>>>(x, dw);
    k_pw_ln_kv<<<NB * KVL, 256>>>(lnw, lnb);
    k_main<<<NB * 128, 512, SMB>>>(x, bproj, out);
}

// round 13
// speedup vs baseline: 1.8597x; 1.1042x over previous
#include <cuda_runtime.h>
#include <cuda_bf16.h>
#include <math.h>
#include <stdint.h>

#define NB 8
#define NC 128
#define NH 8
#define HD 16
#define KVL 85

#define TSTR 272
#define TILEB (128 * TSTR)   // 34816
#define KSTRIDE 144
#define KTILE (96 * KSTRIDE) // rows=kv(96 padded), cols=4 heads x 16c
#define VSTRIDE 208
#define VTILE (64 * VSTRIDE) // rows=4 heads x 16c, cols=j (96 pad 104)

__device__ __align__(16) float d_tab[128 * 64];
__device__ __align__(16) float d_tabT[64 * 128];
__device__ __align__(16) float d_tabR[8 * 64];
__device__ __align__(16) float d_y1[NB * KVL * NC];
__device__ __align__(16) float d_pwT[128 * 128];
__device__ __align__(16) float d_WkvT[128 * 256];
__device__ __align__(16) unsigned char d_wqh[TILEB];
__device__ __align__(16) unsigned char d_wql[TILEB];
__device__ __align__(16) unsigned char d_wph[TILEB];
__device__ __align__(16) unsigned char d_wpl[TILEB];
__device__ __align__(16) unsigned char d_kth[NB * 2 * KTILE];
__device__ __align__(16) unsigned char d_ktl[NB * 2 * KTILE];
__device__ __align__(16) unsigned char d_vth[NB * 2 * VTILE];
__device__ __align__(16) unsigned char d_vtl[NB * 2 * VTILE];

__device__ __forceinline__ uint32_t bf2u(__nv_bfloat162 v) {
    return ((uint32_t)__bfloat16_as_ushort(v.y) << 16) | (uint32_t)__bfloat16_as_ushort(v.x);
}
__device__ __forceinline__ void bfsplit(float v0, float v1, uint32_t& hi, uint32_t& lo) {
    __nv_bfloat162 hh = __floats2bfloat162_rn(v0, v1);
    __nv_bfloat162 ll = __floats2bfloat162_rn(v0 - __bfloat162float(hh.x),
                                              v1 - __bfloat162float(hh.y));
    hi = bf2u(hh); lo = bf2u(ll);
}

// ---------------- K0: tables + transposes + weight split + KV zero ----------
__global__ void k_prep(const float* __restrict__ pw, const float* __restrict__ Wkv,
                       const float* __restrict__ Wq, const float* __restrict__ Wp) {
    int idx = blockIdx.x * 256 + threadIdx.x;
    if (idx < 8192) {
        int yv = idx >> 6, j = idx & 63, i = j & 31;
        float inv = powf(10000.0f, -(2.0f * (float)i) / 64.0f);
        float a = (float)yv * inv;
        d_tab[idx] = (j < 32) ? sinf(a) : cosf(a);
    } else if (idx < 16384) {
        int e = idx - 8192;
        int j = e >> 7, p = e & 127, i = j & 31;
        float inv = powf(10000.0f, -(2.0f * (float)i) / 64.0f);
        float a = (float)p * inv;
        d_tabT[e] = (j < 32) ? sinf(a) : cosf(a);
    } else if (idx < 16896) {
        int e = idx - 16384;
        int bin = e >> 6, j = e & 63, i = j & 31;
        float inv = powf(10000.0f, -(2.0f * (float)i) / 64.0f);
        float s = 0.0f;
        for (int t = 0; t < 16; ++t) {
            float a = (float)(bin * 16 + t) * inv;
            s += (j < 32) ? sinf(a) : cosf(a);
        }
        d_tabR[e] = s;
    } else if (idx < 33280) {
        int e = idx - 16896;
        d_pwT[e] = pw[(e & 127) * 128 + (e >> 7)];
    } else if (idx < 66048) {
        int e = idx - 33280;
        d_WkvT[e] = Wkv[(e & 255) * 128 + (e >> 8)];
    } else if (idx < 98816) {
        int i = idx - 66048;
        const float* W; unsigned char *H, *L; int e;
        if (i < 16384) { W = Wq; H = d_wqh; L = d_wql; e = i; }
        else           { W = Wp; H = d_wph; L = d_wpl; e = i - 16384; }
        int o = e >> 7, c = e & 127;
        float v = W[e];
        __nv_bfloat16 h = __float2bfloat16(v);
        float r = v - __bfloat162float(h);
        uint32_t off = (uint32_t)(o * TSTR + c * 2);
        *(__nv_bfloat16*)(H + off) = h;
        *(__nv_bfloat16*)(L + off) = __float2bfloat16(r);
    } else if (idx < 98816 + 55296) {
        ((uint32_t*)d_kth)[idx - 98816] = 0;
    } else if (idx < 98816 + 110592) {
        ((uint32_t*)d_ktl)[idx - 98816 - 55296] = 0;
    } else if (idx < 98816 + 110592 + 53248) {
        ((uint32_t*)d_vth)[idx - 98816 - 110592] = 0;
    } else if (idx < 98816 + 110592 + 106496) {
        ((uint32_t*)d_vtl)[idx - 98816 - 110592 - 53248] = 0;
    }
}

// ---------------- K1: ASPP pooling + depthwise conv (validated) -------------
__global__ void k_pool_dw(const float* __restrict__ x, const float* __restrict__ dw) {
    __shared__ float pm[64];
    __shared__ float g4[16];
    __shared__ float g2[4];
    __shared__ float g1[1];
    int tid = threadIdx.x;
    int b = blockIdx.x >> 7, c = blockIdx.x & 127;
    if (tid < 64) pm[tid] = 0.0f;
    __syncthreads();
    int r = tid >> 1, hf = tid & 1;
    const float4* xr = (const float4*)(x + ((size_t)(b * NC + c) << 14) + (r << 7) + (hf << 6));
    float sbin[4] = {0.0f, 0.0f, 0.0f, 0.0f};
#pragma unroll
    for (int q = 0; q < 16; ++q) {
        float4 v = xr[q];
        sbin[q >> 2] += (v.x + v.y) + (v.z + v.w);
    }
    int by = r >> 4;
#pragma unroll
    for (int t = 0; t < 4; ++t) atomicAdd(&pm[by * 8 + hf * 4 + t], sbin[t]);
    __syncthreads();
    if (tid < 64) {
        int byy = tid >> 3, bx = tid & 7;
        float pe = (c < 64) ? d_tabR[byy * 64 + c] : d_tabR[bx * 64 + (c - 64)];
        pm[tid] = (pm[tid] + 16.0f * pe) * (1.0f / 256.0f);
    }
    __syncthreads();
    if (tid < 16) {
        int i = tid >> 2, j = tid & 3;
        g4[tid] = 0.25f * (pm[(2 * i) * 8 + 2 * j] + pm[(2 * i) * 8 + 2 * j + 1] +
                           pm[(2 * i + 1) * 8 + 2 * j] + pm[(2 * i + 1) * 8 + 2 * j + 1]);
    } else if (tid < 20) {
        int t = tid - 16, i = t >> 1, j = t & 1;
        float s = 0.0f;
        for (int yy = 0; yy < 4; ++yy)
            for (int xq = 0; xq < 4; ++xq) s += pm[(4 * i + yy) * 8 + 4 * j + xq];
        g2[t] = s * (1.0f / 16.0f);
    } else if (tid == 20) {
        float s = 0.0f;
        for (int q = 0; q < 64; ++q) s += pm[q];
        g1[0] = s * (1.0f / 64.0f);
    }
    __syncthreads();
    if (tid < KVL) {
        float wv[9];
#pragma unroll
        for (int q = 0; q < 9; ++q) wv[q] = dw[c * 9 + q];
        const float* g; int s, ly, lx;
        if (tid < 64)      { g = pm; s = 8; ly = tid >> 3;        lx = tid & 7; }
        else if (tid < 80) { int t = tid - 64; g = g4; s = 4; ly = t >> 2; lx = t & 3; }
        else if (tid < 84) { int t = tid - 80; g = g2; s = 2; ly = t >> 1; lx = t & 1; }
        else               { g = g1; s = 1; ly = 0; lx = 0; }
        float a = 0.0f;
#pragma unroll
        for (int ky = 0; ky < 3; ++ky) {
            int iy = ly + ky - 1;
            bool oky = (iy >= 0) && (iy < s);
#pragma unroll
            for (int kx = 0; kx < 3; ++kx) {
                int ix = lx + kx - 1;
                if (oky && ix >= 0 && ix < s) a += g[iy * s + ix] * wv[ky * 3 + kx];
            }
        }
        d_y1[((size_t)b * KVL + tid) * NC + c] = a;
    }
}

// ---------------- K2: pointwise -> LN -> GELU -> KV proj (bf16 tiles) -------
__global__ void k_pw_ln_kv(const float* __restrict__ lnw, const float* __restrict__ lnb) {
    __shared__ float ycol[128];
    __shared__ float part[256];
    __shared__ float zs[128];
    __shared__ float red[2];
    int tid = threadIdx.x;
    int b = blockIdx.x / KVL;
    int row = blockIdx.x - b * KVL;
    if (tid < 128) ycol[tid] = d_y1[((size_t)b * KVL + row) * NC + tid];
    __syncthreads();
    {
        int o = tid & 127, half = tid >> 7;
        const float* wc = d_pwT + (half << 6) * 128 + o;
        const float* yc = ycol + (half << 6);
        float a = 0.0f;
#pragma unroll 8
        for (int ci = 0; ci < 64; ++ci) a += wc[ci * 128] * yc[ci];
        part[tid] = a;
    }
    __syncthreads();
    if (tid < 128) zs[tid] = part[tid] + part[tid + 128];
    __syncthreads();
    if (tid < 32) {
        float s = zs[tid] + zs[tid + 32] + zs[tid + 64] + zs[tid + 96];
#pragma unroll
        for (int o = 16; o; o >>= 1) s += __shfl_xor_sync(0xffffffffu, s, o);
        if (tid == 0) red[0] = s * (1.0f / 128.0f);
    }
    __syncthreads();
    float mu = red[0];
    if (tid < 32) {
        float s = 0.0f;
#pragma unroll
        for (int q = 0; q < 4; ++q) { float dd = zs[tid + 32 * q] - mu; s += dd * dd; }
#pragma unroll
        for (int o = 16; o; o >>= 1) s += __shfl_xor_sync(0xffffffffu, s, o);
        if (tid == 0) red[1] = s * (1.0f / 128.0f);
    }
    __syncthreads();
    float rstd = rsqrtf(red[1] + 1e-5f);
    if (tid < 128) {
        float zn = (zs[tid] - mu) * rstd * lnw[tid] + lnb[tid];
        zs[tid] = 0.5f * zn * (1.0f + erff(zn * 0.70710678118654752f));
    }
    __syncthreads();
    float a = 0.0f;
    const float* wc = d_WkvT + tid;
#pragma unroll 8
    for (int ci = 0; ci < 128; ++ci) a += wc[ci * 256] * zs[ci];
    __nv_bfloat16 h = __float2bfloat16(a);
    __nv_bfloat16 l = __float2bfloat16(a - __bfloat162float(h));
    if (tid < 128) {       // K: rows=kv, cols=(head&3)*16+d, stage=head>>2
        int m = tid >> 4, d = tid & 15, s = m >> 2;
        uint32_t off = ((uint32_t)(b * 2 + s) * 96 + row) * KSTRIDE + (m & 3) * 32 + d * 2;
        *(__nv_bfloat16*)(d_kth + off) = h;
        *(__nv_bfloat16*)(d_ktl + off) = l;
    } else {               // V^T: rows=(head&3)*16+d, cols=j
        int cc = tid - 128;
        int m = cc >> 4, d = cc & 15, s = m >> 2;
        uint32_t off = ((uint32_t)(b * 2 + s) * 64 + (m & 3) * 16 + d) * VSTRIDE + row * 2;
        *(__nv_bfloat16*)(d_vth + off) = h;
        *(__nv_bfloat16*)(d_vtl + off) = l;
    }
}

// ---------------- K3: fused main — HMMA everywhere, 1024 threads ------------
#define OXH 0
#define OXL TILEB
#define OWH (2 * TILEB)
#define OWL (3 * TILEB)
#define OKH (4 * TILEB)
#define OKL (OKH + KTILE)
#define OVH (OKL + KTILE)
#define OVL (OVH + VTILE)
#define OBI (OVL + VTILE)
#define SMB (OBI + 512 + 64)

#define LDMX4(r0, r1, r2, r3, a) \
    asm volatile("ldmatrix.sync.aligned.m8n8.x4.shared.b16 {%0,%1,%2,%3}, [%4];" \
        : "=r"(r0), "=r"(r1), "=r"(r2), "=r"(r3) : "r"(a))
#define LDMX2(r0, r1, a) \
    asm volatile("ldmatrix.sync.aligned.m8n8.x2.shared.b16 {%0,%1}, [%2];" \
        : "=r"(r0), "=r"(r1) : "r"(a))
#define MMA16816(d, a0, a1, a2, a3, b0, b1) \
    asm volatile("mma.sync.aligned.m16n8k16.row.col.f32.bf16.bf16.f32 " \
        "{%0,%1,%2,%3}, {%4,%5,%6,%7}, {%8,%9}, {%0,%1,%2,%3};" \
        : "+f"((d)[0]), "+f"((d)[1]), "+f"((d)[2]), "+f"((d)[3]) \
        : "r"(a0), "r"(a1), "r"(a2), "r"(a3), "r"(b0), "r"(b1))

// D[m=A-rows][n=B-rows]: 32 warps, mt=w&7 (16 A-rows), nq=w>>3 (32 B-rows)
__device__ __forceinline__ void hmma_gemm(uint32_t sb, uint32_t aBase, uint32_t bBase,
                                          int w, int lane, float D[4][4]) {
#pragma unroll
    for (int n = 0; n < 4; ++n)
#pragma unroll
        for (int q = 0; q < 4; ++q) D[n][q] = 0.0f;
    int mt = w & 7, nq = w >> 3;
    int sub = lane >> 3, r = lane & 7;
    uint32_t aH = sb + aBase + (uint32_t)((mt * 16 + (sub & 1) * 8 + r) * TSTR + (sub >> 1) * 16);
    uint32_t aL = aH + TILEB;
    int bl = lane & 15;
    uint32_t bH = sb + bBase + (uint32_t)((nq * 32 + (bl & 7)) * TSTR + (bl >> 3) * 16);
    uint32_t bL = bH + TILEB;
#pragma unroll
    for (int kc = 0; kc < 8; ++kc) {
        uint32_t ah0, ah1, ah2, ah3, al0, al1, al2, al3;
        LDMX4(ah0, ah1, ah2, ah3, aH + kc * 32);
        LDMX4(al0, al1, al2, al3, aL + kc * 32);
#pragma unroll
        for (int n = 0; n < 4; ++n) {
            uint32_t bh0, bh1, bl0, bl1;
            LDMX2(bh0, bh1, bH + n * (8 * TSTR) + kc * 32);
            LDMX2(bl0, bl1, bL + n * (8 * TSTR) + kc * 32);
            MMA16816(D[n], ah0, ah1, ah2, ah3, bh0, bh1);
            MMA16816(D[n], al0, al1, al2, al3, bh0, bh1);
            MMA16816(D[n], ah0, ah1, ah2, ah3, bl0, bl1);
        }
    }
}

__device__ __forceinline__ void fill_kv(char* smc, int tid, int b, int s) {
    const float4* kh = (const float4*)(d_kth + (size_t)(b * 2 + s) * KTILE);
    const float4* kl = (const float4*)(d_ktl + (size_t)(b * 2 + s) * KTILE);
    const float4* vh = (const float4*)(d_vth + (size_t)(b * 2 + s) * VTILE);
    const float4* vl = (const float4*)(d_vtl + (size_t)(b * 2 + s) * VTILE);
    float4* dkh = (float4*)(smc + OKH);
    float4* dkl = (float4*)(smc + OKL);
    float4* dvh = (float4*)(smc + OVH);
    float4* dvl = (float4*)(smc + OVL);
    for (int i = tid; i < KTILE / 16; i += 1024) { dkh[i] = kh[i]; dkl[i] = kl[i]; }
    for (int i = tid; i < VTILE / 16; i += 1024) { dvh[i] = vh[i]; dvl[i] = vl[i]; }
}

__global__ void __launch_bounds__(1024, 1)
k_main(const float* __restrict__ x, const float* __restrict__ bproj,
       float* __restrict__ out) {
    extern __shared__ char smc[];
    uint32_t sb;
    asm("{ .reg .u64 t; cvta.to.shared.u64 t, %1; cvt.u32.u64 %0, t; }" : "=r"(sb) : "l"(smc));
    int tid = threadIdx.x, w = tid >> 5, lane = tid & 31;
    int b = blockIdx.x >> 7, y = blockIdx.x & 127;

    if (tid < 128) ((float*)(smc + OBI))[tid] = bproj[tid];
    {   // Wq tiles
        const float4* h4 = (const float4*)d_wqh;
        const float4* l4 = (const float4*)d_wql;
        float4* wh = (float4*)(smc + OWH);
        float4* wl = (float4*)(smc + OWL);
        for (int i = tid; i < TILEB / 16; i += 1024) { wh[i] = h4[i]; wl[i] = l4[i]; }
    }
    {   // Xp bf16 split tiles: rows=px, cols=c
        int p = tid & 127;
        int yoff = y << 7;
        for (int g = tid >> 7; g < 64; g += 8) {
            int c0 = g * 2, c1 = c0 + 1;
            float v0 = x[((size_t)(b * NC + c0) << 14) + yoff + p];
            float v1 = x[((size_t)(b * NC + c1) << 14) + yoff + p];
            v0 += (c0 < 64) ? d_tab[y * 64 + c0] : d_tabT[(c0 - 64) * 128 + p];
            v1 += (c1 < 64) ? d_tab[y * 64 + c1] : d_tabT[(c1 - 64) * 128 + p];
            uint32_t hi, lo;
            bfsplit(v0, v1, hi, lo);
            uint32_t off = (uint32_t)(p * TSTR + c0 * 2);
            *(uint32_t*)(smc + OXH + off) = hi;
            *(uint32_t*)(smc + OXL + off) = lo;
        }
    }
    fill_kv(smc, tid, b, 0);
    __syncthreads();

    float D[4][4];
    // ---- Q-GEMM: D[px][c] (A = X, B = Wq) ----
    hmma_gemm(sb, OXH, OWH, w, lane, D);
    __syncthreads();   // Wq reads done

    int sub = lane >> 3, r8 = lane & 7, bl = lane & 15, q = lane & 3, rr = lane >> 2;
    {   // write Q bf16 hi/lo (x0.25) into OWH/OWL, rows=px cols=c
        int mt = w & 7, nq = w >> 3;
        int px0 = mt * 16 + rr;
#pragma unroll
        for (int n = 0; n < 4; ++n) {
            int c = nq * 32 + n * 8 + q * 2;
            uint32_t hi, lo;
            bfsplit(D[n][0] * 0.25f, D[n][1] * 0.25f, hi, lo);
            *(uint32_t*)(smc + OWH + px0 * TSTR + c * 2) = hi;
            *(uint32_t*)(smc + OWL + px0 * TSTR + c * 2) = lo;
            bfsplit(D[n][2] * 0.25f, D[n][3] * 0.25f, hi, lo);
            *(uint32_t*)(smc + OWH + (px0 + 8) * TSTR + c * 2) = hi;
            *(uint32_t*)(smc + OWL + (px0 + 8) * TSTR + c * 2) = lo;
        }
    }
    __syncthreads();

    // ---- attention: 2 stages; task/warp = (head hl, 16-px tile mt) ----
    for (int s = 0; s < 2; ++s) {
        if (s) { __syncthreads(); fill_kv(smc, tid, b, 1); __syncthreads(); }
        {
            int hl = w >> 3, mt = w & 7;
            int h = s * 4 + hl;
            uint32_t qa = sb + OWH + (uint32_t)((mt * 16 + (sub & 1) * 8 + r8) * TSTR
                        + h * 32 + (sub >> 1) * 16);
            uint32_t qh0, qh1, qh2, qh3, ql0, ql1, ql2, ql3;
            LDMX4(qh0, qh1, qh2, qh3, qa);
            LDMX4(ql0, ql1, ql2, ql3, qa + TILEB);
            uint32_t kbase = sb + OKH + (uint32_t)((bl & 7) * KSTRIDE + hl * 32 + (bl >> 3) * 16);
            uint32_t vbase = sb + OVH + (uint32_t)((hl * 16 + (bl & 7)) * VSTRIDE + (bl >> 3) * 16);
            float o0[4] = {0, 0, 0, 0}, o1[4] = {0, 0, 0, 0};
            float sr = 0.0f, sr8 = 0.0f;
#pragma unroll
            for (int ks = 0; ks < 6; ++ks) {
                float P0[4] = {0, 0, 0, 0}, P1[4] = {0, 0, 0, 0};
                uint32_t kh0, kh1, kl0, kl1;
                LDMX2(kh0, kh1, kbase + (2 * ks) * (8 * KSTRIDE));
                LDMX2(kl0, kl1, kbase + (2 * ks) * (8 * KSTRIDE) + (OKL - OKH));
                MMA16816(P0, qh0, qh1, qh2, qh3, kh0, kh1);
                MMA16816(P0, ql0, ql1, ql2, ql3, kh0, kh1);
                MMA16816(P0, qh0, qh1, qh2, qh3, kl0, kl1);
                LDMX2(kh0, kh1, kbase + (2 * ks + 1) * (8 * KSTRIDE));
                LDMX2(kl0, kl1, kbase + (2 * ks + 1) * (8 * KSTRIDE) + (OKL - OKH));
                MMA16816(P1, qh0, qh1, qh2, qh3, kh0, kh1);
                MMA16816(P1, ql0, ql1, ql2, ql3, kh0, kh1);
                MMA16816(P1, qh0, qh1, qh2, qh3, kl0, kl1);
                float e00 = __expf(P0[0]), e01 = __expf(P0[1]);
                float e02 = __expf(P0[2]), e03 = __expf(P0[3]);
                float e10 = __expf(P1[0]), e11 = __expf(P1[1]);
                float e12 = __expf(P1[2]), e13 = __expf(P1[3]);
                sr += (e00 + e01) + (e10 + e11);
                sr8 += (e02 + e03) + (e12 + e13);
                uint32_t ah0, ah1, ah2, ah3, al0, al1, al2, al3;
                bfsplit(e00, e01, ah0, al0);
                bfsplit(e02, e03, ah1, al1);
                bfsplit(e10, e11, ah2, al2);
                bfsplit(e12, e13, ah3, al3);
                uint32_t vh0, vh1, vl0, vl1;
                LDMX2(vh0, vh1, vbase + ks * 32);
                LDMX2(vl0, vl1, vbase + ks * 32 + (OVL - OVH));
                MMA16816(o0, ah0, ah1, ah2, ah3, vh0, vh1);
                MMA16816(o0, al0, al1, al2, al3, vh0, vh1);
                MMA16816(o0, ah0, ah1, ah2, ah3, vl0, vl1);
                LDMX2(vh0, vh1, vbase + 8 * VSTRIDE + ks * 32);
                LDMX2(vl0, vl1, vbase + 8 * VSTRIDE + ks * 32 + (OVL - OVH));
                MMA16816(o1, ah0, ah1, ah2, ah3, vh0, vh1);
                MMA16816(o1, al0, al1, al2, al3, vh0, vh1);
                MMA16816(o1, ah0, ah1, ah2, ah3, vl0, vl1);
            }
            sr += __shfl_xor_sync(0xffffffffu, sr, 1);
            sr += __shfl_xor_sync(0xffffffffu, sr, 2);
            sr8 += __shfl_xor_sync(0xffffffffu, sr8, 1);
            sr8 += __shfl_xor_sync(0xffffffffu, sr8, 2);
            float ir = 1.0f / (sr - 11.0f), ir8 = 1.0f / (sr8 - 11.0f);
            int px0 = (w & 7) * 16 + rr;
            int c0 = h * 16 + q * 2;
            uint32_t hi, lo;
            bfsplit(o0[0] * ir, o0[1] * ir, hi, lo);
            *(uint32_t*)(smc + OXH + px0 * TSTR + c0 * 2) = hi;
            *(uint32_t*)(smc + OXL + px0 * TSTR + c0 * 2) = lo;
            bfsplit(o0[2] * ir8, o0[3] * ir8, hi, lo);
            *(uint32_t*)(smc + OXH + (px0 + 8) * TSTR + c0 * 2) = hi;
            *(uint32_t*)(smc + OXL + (px0 + 8) * TSTR + c0 * 2) = lo;
            bfsplit(o1[0] * ir, o1[1] * ir, hi, lo);
            *(uint32_t*)(smc + OXH + px0 * TSTR + (c0 + 8) * 2) = hi;
            *(uint32_t*)(smc + OXL + px0 * TSTR + (c0 + 8) * 2) = lo;
            bfsplit(o1[2] * ir8, o1[3] * ir8, hi, lo);
            *(uint32_t*)(smc + OXH + (px0 + 8) * TSTR + (c0 + 8) * 2) = hi;
            *(uint32_t*)(smc + OXL + (px0 + 8) * TSTR + (c0 + 8) * 2) = lo;
        }
    }
    __syncthreads();
    {   // Wproj tiles (Q dead)
        const float4* h4 = (const float4*)d_wph;
        const float4* l4 = (const float4*)d_wpl;
        float4* wh = (float4*)(smc + OWH);
        float4* wl = (float4*)(smc + OWL);
        for (int i = tid; i < TILEB / 16; i += 1024) { wh[i] = h4[i]; wl[i] = l4[i]; }
    }
    __syncthreads();

    // ---- out-proj GEMM: D[px][c] (A = O, B = Wproj) + bias + store ----
    hmma_gemm(sb, OXH, OWH, w, lane, D);
    {
        const float* bias = (const float*)(smc + OBI);
        int mt = w & 7, nq = w >> 3;
        int px0 = mt * 16 + rr;
        float* og = out + (((size_t)b * NC) << 14) + (y << 7);
#pragma unroll
        for (int n = 0; n < 4; ++n) {
            int c0 = nq * 32 + n * 8 + q * 2;
            float b0 = bias[c0], b1 = bias[c0 + 1];
            float* p0 = og + (((size_t)c0) << 14);
            float* p1 = og + (((size_t)(c0 + 1)) << 14);
            p0[px0] = D[n][0] + b0;
            p1[px0] = D[n][1] + b1;
            p0[px0 + 8] = D[n][2] + b0;
            p1[px0 + 8] = D[n][3] + b1;
        }
    }
}

// ----------------------------------------------------------------------------
extern "C" void kernel_launch(void* const* d_in, const int* in_sizes, int n_in,
                              void* d_out, int out_size) {
    const float* x     = (const float*)d_in[0];
    const float* Wq    = (const float*)d_in[1];
    const float* Wkv   = (const float*)d_in[2];
    const float* Wproj = (const float*)d_in[3];
    const float* bproj = (const float*)d_in[4];
    const float* dw    = (const float*)d_in[5];
    const float* pw    = (const float*)d_in[6];
    const float* lnw   = (const float*)d_in[7];
    const float* lnb   = (const float*)d_in[8];
    float* out = (float*)d_out;

    cudaFuncSetAttribute(k_main, cudaFuncAttributeMaxDynamicSharedMemorySize, SMB);

    k_prep<<<1234, 256>>>(pw, Wkv, Wq, Wproj);
    k_pool_dw<<<NB * NC, 256>>>(x, dw);
    k_pw_ln_kv<<<NB * KVL, 256>>>(lnw, lnb);
    k_main<<<NB * 128, 1024, SMB>>>(x, bproj, out);
}